// round 13
// baseline (speedup 1.0000x reference)
#include <cuda_runtime.h>
#include <cuda_bf16.h>
#include <math.h>
#include <stdint.h>

#define BATCH   2
#define SEQ     2048
#define DMODEL  1024
#define NHEADS  16
#define DK      64
#define MROWS   (BATCH * SEQ)   // 4096

// -------------------- scratch (__device__ globals; no allocations) ---------
// int8 slices (q1, q2) + per-row reconstruction scales (alpha/127)
__device__ int8_t g_X1[(size_t)MROWS * DMODEL];
__device__ int8_t g_X2[(size_t)MROWS * DMODEL];
__device__ float  g_sX[MROWS];
__device__ int8_t g_W1[4][(size_t)DMODEL * DMODEL];   // q,k,v,o  [out_feat][k]
__device__ int8_t g_W2[4][(size_t)DMODEL * DMODEL];
__device__ float  g_sW[4][DMODEL];
// Q/K/V bf16 hi/lo splits, [b,h,s,dk] (attention path unchanged)
__device__ __nv_bfloat16 g_qh[(size_t)BATCH * NHEADS * SEQ * DK];
__device__ __nv_bfloat16 g_ql[(size_t)BATCH * NHEADS * SEQ * DK];
__device__ __nv_bfloat16 g_kh[(size_t)BATCH * NHEADS * SEQ * DK];
__device__ __nv_bfloat16 g_kl[(size_t)BATCH * NHEADS * SEQ * DK];
__device__ __nv_bfloat16 g_vh[(size_t)BATCH * NHEADS * SEQ * DK];
__device__ __nv_bfloat16 g_vl[(size_t)BATCH * NHEADS * SEQ * DK];
// attention output fp32 (concat [m,d]) + its int8 slices
__device__ float  g_O[(size_t)MROWS * DMODEL];
__device__ int8_t g_O1[(size_t)MROWS * DMODEL];
__device__ int8_t g_O2[(size_t)MROWS * DMODEL];
__device__ float  g_sO[MROWS];

// readiness counters (zeroed by cvt kernel each call)
__device__ int g_cntPair[8];   // qkv CTAs done per head-pair (target 96)
__device__ int g_cntO[32];     // attn CTAs done per (b,qt) m-block (target 16)
__device__ int g_cntQO[32];    // cvt-O done per m-block (target 1)

// ===========================================================================
// warp-MMA helpers (arch-portable sm_80+ ISA)
// ===========================================================================
__device__ __forceinline__ uint32_t smem_u32(const void* p) {
    uint32_t a;
    asm("{ .reg .u64 t; cvta.to.shared.u64 t, %1; cvt.u32.u64 %0, t; }"
        : "=r"(a) : "l"(p));
    return a;
}

__device__ __forceinline__ void ldsm_x4(uint32_t& r0, uint32_t& r1,
                                        uint32_t& r2, uint32_t& r3, uint32_t addr) {
    asm volatile("ldmatrix.sync.aligned.m8n8.x4.shared.b16 {%0,%1,%2,%3}, [%4];"
                 : "=r"(r0), "=r"(r1), "=r"(r2), "=r"(r3) : "r"(addr));
}

__device__ __forceinline__ void ldsm_x4t(uint32_t& r0, uint32_t& r1,
                                         uint32_t& r2, uint32_t& r3, uint32_t addr) {
    asm volatile("ldmatrix.sync.aligned.m8n8.x4.trans.shared.b16 {%0,%1,%2,%3}, [%4];"
                 : "=r"(r0), "=r"(r1), "=r"(r2), "=r"(r3) : "r"(addr));
}

__device__ __forceinline__ void mma16816(float* d, const uint32_t* a, const uint32_t* b) {
    asm volatile(
        "mma.sync.aligned.m16n8k16.row.col.f32.bf16.bf16.f32 "
        "{%0,%1,%2,%3}, {%4,%5,%6,%7}, {%8,%9}, {%0,%1,%2,%3};"
        : "+f"(d[0]), "+f"(d[1]), "+f"(d[2]), "+f"(d[3])
        : "r"(a[0]), "r"(a[1]), "r"(a[2]), "r"(a[3]), "r"(b[0]), "r"(b[1]));
}

__device__ __forceinline__ void mma16832s8(int* d, const uint32_t* a, const uint32_t* b) {
    asm volatile(
        "mma.sync.aligned.m16n8k32.row.col.s32.s8.s8.s32 "
        "{%0,%1,%2,%3}, {%4,%5,%6,%7}, {%8,%9}, {%0,%1,%2,%3};"
        : "+r"(d[0]), "+r"(d[1]), "+r"(d[2]), "+r"(d[3])
        : "r"(a[0]), "r"(a[1]), "r"(a[2]), "r"(a[3]), "r"(b[0]), "r"(b[1]));
}

__device__ __forceinline__ float ex2f(float x) {
    float r;
    asm("ex2.approx.f32 %0, %1;" : "=f"(r) : "f"(x));
    return r;
}

__device__ __forceinline__ void split2(float x, float y, uint32_t& hi, uint32_t& lo) {
    uint32_t h;
    asm("cvt.rn.bf16x2.f32 %0, %1, %2;" : "=r"(h) : "f"(y), "f"(x));
    const float hx = __uint_as_float(h << 16);
    const float hy = __uint_as_float(h & 0xFFFF0000u);
    const float rx = x - hx, ry = y - hy;
    uint32_t l;
    asm("cvt.rn.bf16x2.f32 %0, %1, %2;" : "=r"(l) : "f"(ry), "f"(rx));
    hi = h; lo = l;
}

__device__ __forceinline__ int ld_acq(const int* p) {
    int v;
    asm volatile("ld.acquire.gpu.b32 %0, [%1];" : "=r"(v) : "l"(p) : "memory");
    return v;
}

// slice 4 floats into packed q1 (7-bit) and q2 (next 8 bits), given inv = 127/alpha
__device__ __forceinline__ void q2pack(const float* f, float inv,
                                       uint32_t& u1, uint32_t& u2) {
    u1 = 0; u2 = 0;
#pragma unroll
    for (int j = 0; j < 4; j++) {
        const float p  = f[j] * inv;          // |p| <= 127
        const float f1 = rintf(p);
        const int   a1 = (int)f1;
        int a2 = (int)rintf((p - f1) * 256.0f);
        a2 = min(a2, 127);                    // +128 edge -> clamp
        u1 |= (uint32_t)(a1 & 255) << (8 * j);
        u2 |= (uint32_t)(a2 & 255) << (8 * j);
    }
}

// ===========================================================================
// cvt: slice X and all 4 W into int8 (one warp per row); zero counters
// ===========================================================================
__global__ void cvt_s8_kernel(const float* __restrict__ x,
                              const float* __restrict__ wq,
                              const float* __restrict__ wk,
                              const float* __restrict__ wv,
                              const float* __restrict__ wo)
{
    const int tid = threadIdx.x;
    if (blockIdx.x == 0 && tid < 72) {
        if      (tid < 8)  g_cntPair[tid] = 0;
        else if (tid < 40) g_cntO[tid - 8] = 0;
        else               g_cntQO[tid - 40] = 0;
    }
    const int wgl  = blockIdx.x * 8 + (tid >> 5);   // global warp = row id
    const int lane = tid & 31;

    const float* src;
    int8_t *d1, *d2;
    float* sc;
    if (wgl < MROWS) {
        src = x + (size_t)wgl * DMODEL;
        d1 = g_X1 + (size_t)wgl * DMODEL;
        d2 = g_X2 + (size_t)wgl * DMODEL;
        sc = &g_sX[wgl];
    } else {
        const int t = wgl - MROWS;
        const int z = t >> 10, n = t & 1023;
        const float* w = (z == 0) ? wq : (z == 1) ? wk : (z == 2) ? wv : wo;
        src = w + (size_t)n * DMODEL;
        d1 = g_W1[z] + (size_t)n * DMODEL;
        d2 = g_W2[z] + (size_t)n * DMODEL;
        sc = &g_sW[z][n];
    }

    float4 v[8];
    float mx = 0.0f;
#pragma unroll
    for (int i = 0; i < 8; i++) {
        v[i] = ((const float4*)src)[i * 32 + lane];
        mx = fmaxf(mx, fmaxf(fmaxf(fabsf(v[i].x), fabsf(v[i].y)),
                             fmaxf(fabsf(v[i].z), fabsf(v[i].w))));
    }
#pragma unroll
    for (int s = 16; s > 0; s >>= 1)
        mx = fmaxf(mx, __shfl_xor_sync(0xffffffffu, mx, s));

    const float inv = 127.0f / fmaxf(mx, 1e-30f);
    if (lane == 0) *sc = mx * (1.0f / 127.0f);

#pragma unroll
    for (int i = 0; i < 8; i++) {
        uint32_t u1, u2;
        q2pack((const float*)&v[i], inv, u1, u2);
        ((uint32_t*)d1)[i * 32 + lane] = u1;
        ((uint32_t*)d2)[i * 32 + lane] = u2;
    }
}

// ===========================================================================
// INT8 split GEMM core: C[128,128] tile of A[.,K]·B[.,K]^T.
// d11 = q1·p1 ; dlo = q1·p2 + q2·p1 (both weight 2^-8). K-chunks of 64 s8.
// smem row stride 80 B — byte-identical conflict-free pattern to the
// validated bf16 core (2 s8 per b16 lane).
// ===========================================================================
__device__ __forceinline__ void gemm_tile_s8(
    const int8_t* __restrict__ A1, const int8_t* __restrict__ A2,
    const int8_t* __restrict__ B1, const int8_t* __restrict__ B2,
    int m0, int n0, int d11[2][8][4], int dlo[2][8][4], char* sbuf)
{
    char* sA1 = sbuf;
    char* sA2 = sbuf + 10240;
    char* sB1 = sbuf + 20480;
    char* sB2 = sbuf + 30720;

    const int tid  = threadIdx.x;
    const int lane = tid & 31;
    const int wid  = tid >> 5;
    const int wm   = wid >> 1;
    const int wn   = wid & 1;

    const uint32_t aA1 = smem_u32(sA1), aA2 = smem_u32(sA2);
    const uint32_t aB1 = smem_u32(sB1), aB2 = smem_u32(sB2);

    const int sub  = lane >> 3, l7 = lane & 7;
    const int arow = wm * 32 + l7 + (sub & 1) * 8;
    const int akof = (sub >> 1) * 16;            // bytes
    const int brow = wn * 64 + l7 + (sub >> 1) * 8;
    const int bkof = (sub & 1) * 16;             // bytes

    const int grow = tid >> 2;                   // 0..63
    const int gb   = (tid & 3) * 16;             // byte offset in 64B row chunk

#pragma unroll
    for (int mt = 0; mt < 2; mt++)
#pragma unroll
        for (int nt = 0; nt < 8; nt++)
#pragma unroll
            for (int c = 0; c < 4; c++) { d11[mt][nt][c] = 0; dlo[mt][nt][c] = 0; }

    uint4 va[2][4];
#pragma unroll
    for (int p = 0; p < 2; p++) {
        const size_t ga = (size_t)(m0 + p * 64 + grow) * DMODEL + gb;
        const size_t gbn = (size_t)(n0 + p * 64 + grow) * DMODEL + gb;
        va[p][0] = *(const uint4*)(A1 + ga);
        va[p][1] = *(const uint4*)(A2 + ga);
        va[p][2] = *(const uint4*)(B1 + gbn);
        va[p][3] = *(const uint4*)(B2 + gbn);
    }

    for (int it = 0; it < DMODEL / 64; it++) {
        __syncthreads();
#pragma unroll
        for (int p = 0; p < 2; p++) {
            const int so = (p * 64 + grow) * 80 + gb;
            *(uint4*)(sA1 + so) = va[p][0];
            *(uint4*)(sA2 + so) = va[p][1];
            *(uint4*)(sB1 + so) = va[p][2];
            *(uint4*)(sB2 + so) = va[p][3];
        }
        if (it + 1 < DMODEL / 64) {
            const int k0 = (it + 1) * 64;
#pragma unroll
            for (int p = 0; p < 2; p++) {
                const size_t ga = (size_t)(m0 + p * 64 + grow) * DMODEL + k0 + gb;
                const size_t gbn = (size_t)(n0 + p * 64 + grow) * DMODEL + k0 + gb;
                va[p][0] = *(const uint4*)(A1 + ga);
                va[p][1] = *(const uint4*)(A2 + ga);
                va[p][2] = *(const uint4*)(B1 + gbn);
                va[p][3] = *(const uint4*)(B2 + gbn);
            }
        }
        __syncthreads();

#pragma unroll
        for (int ks = 0; ks < 2; ks++) {        // 2 x k32 per 64-chunk
            uint32_t fA1[2][4], fA2[2][4], fB1[8][2], fB2[8][2];
#pragma unroll
            for (int mt = 0; mt < 2; mt++) {
                const uint32_t off = (uint32_t)((arow + mt * 16) * 80 + ks * 32 + akof);
                ldsm_x4(fA1[mt][0], fA1[mt][1], fA1[mt][2], fA1[mt][3], aA1 + off);
                ldsm_x4(fA2[mt][0], fA2[mt][1], fA2[mt][2], fA2[mt][3], aA2 + off);
            }
#pragma unroll
            for (int g = 0; g < 4; g++) {
                const uint32_t off = (uint32_t)((brow + g * 16) * 80 + ks * 32 + bkof);
                ldsm_x4(fB1[2 * g][0], fB1[2 * g][1], fB1[2 * g + 1][0], fB1[2 * g + 1][1], aB1 + off);
                ldsm_x4(fB2[2 * g][0], fB2[2 * g][1], fB2[2 * g + 1][0], fB2[2 * g + 1][1], aB2 + off);
            }
#pragma unroll
            for (int mt = 0; mt < 2; mt++)
#pragma unroll
                for (int nt = 0; nt < 8; nt++) {
                    mma16832s8(d11[mt][nt], fA1[mt], fB1[nt]);
                    mma16832s8(dlo[mt][nt], fA1[mt], fB2[nt]);
                    mma16832s8(dlo[mt][nt], fA2[mt], fB1[nt]);
                }
        }
    }
}

// ---------------- qkv role: int8 GEMM, epilogue -> bf16 hi/lo [b,h,s,dk] ---
__device__ __forceinline__ void qkv_work(char* sbuf, int z, int m0, int n0)
{
    int d11[2][8][4], dlo[2][8][4];
    gemm_tile_s8(g_X1, g_X2, g_W1[z], g_W2[z], m0, n0, d11, dlo, sbuf);

    __nv_bfloat16* dh = (z == 0) ? g_qh : (z == 1 ? g_kh : g_vh);
    __nv_bfloat16* dl = (z == 0) ? g_ql : (z == 1 ? g_kl : g_vl);
    const int lane = threadIdx.x & 31, wid = threadIdx.x >> 5;
    const int wm = wid >> 1, wn = wid & 1;
#pragma unroll
    for (int mt = 0; mt < 2; mt++) {
        const int r0 = m0 + wm * 32 + mt * 16 + (lane >> 2);
        const float sa0 = g_sX[r0], sa1 = g_sX[r0 + 8];
        const int b = r0 >> 11;
        const int s = r0 & (SEQ - 1);
#pragma unroll
        for (int nt = 0; nt < 8; nt++) {
            const int e  = n0 + wn * 64 + nt * 8 + (lane & 3) * 2;
            const float sb0 = g_sW[z][e], sb1 = g_sW[z][e + 1];
            const float c0 = sa0 * sb0 * ((float)d11[mt][nt][0] + (float)dlo[mt][nt][0] * 0.00390625f);
            const float c1 = sa0 * sb1 * ((float)d11[mt][nt][1] + (float)dlo[mt][nt][1] * 0.00390625f);
            const float c2 = sa1 * sb0 * ((float)d11[mt][nt][2] + (float)dlo[mt][nt][2] * 0.00390625f);
            const float c3 = sa1 * sb1 * ((float)d11[mt][nt][3] + (float)dlo[mt][nt][3] * 0.00390625f);
            const int h  = e >> 6, dk = e & 63;
            const size_t i0 = (((size_t)b * NHEADS + h) * SEQ + s) * DK + dk;
            uint32_t hi, lo;
            split2(c0, c1, hi, lo);
            *(uint32_t*)(dh + i0) = hi;
            *(uint32_t*)(dl + i0) = lo;
            split2(c2, c3, hi, lo);
            *(uint32_t*)(dh + i0 + 8 * DK) = hi;
            *(uint32_t*)(dl + i0 + 8 * DK) = lo;
        }
    }
}

// ---------------- out-proj role: int8 GEMM + bias ---------------------------
__device__ __forceinline__ void out_work(char* sbuf, int m0, int n0,
                                         const float* __restrict__ bias,
                                         float* __restrict__ out)
{
    int d11[2][8][4], dlo[2][8][4];
    gemm_tile_s8(g_O1, g_O2, g_W1[3], g_W2[3], m0, n0, d11, dlo, sbuf);

    const int lane = threadIdx.x & 31, wid = threadIdx.x >> 5;
    const int wm = wid >> 1, wn = wid & 1;
#pragma unroll
    for (int mt = 0; mt < 2; mt++) {
        const int r0 = m0 + wm * 32 + mt * 16 + (lane >> 2);
        const float sa0 = g_sO[r0], sa1 = g_sO[r0 + 8];
#pragma unroll
        for (int nt = 0; nt < 8; nt++) {
            const int e = n0 + wn * 64 + nt * 8 + (lane & 3) * 2;
            const float sb0 = g_sW[3][e], sb1 = g_sW[3][e + 1];
            const float b0 = bias[e], b1 = bias[e + 1];
            const float c0 = sa0 * sb0 * ((float)d11[mt][nt][0] + (float)dlo[mt][nt][0] * 0.00390625f) + b0;
            const float c1 = sa0 * sb1 * ((float)d11[mt][nt][1] + (float)dlo[mt][nt][1] * 0.00390625f) + b1;
            const float c2 = sa1 * sb0 * ((float)d11[mt][nt][2] + (float)dlo[mt][nt][2] * 0.00390625f) + b0;
            const float c3 = sa1 * sb1 * ((float)d11[mt][nt][3] + (float)dlo[mt][nt][3] * 0.00390625f) + b1;
            float* p0 = out + (size_t)r0 * DMODEL + e;
            *(float2*)p0                = make_float2(c0, c1);
            *(float2*)(p0 + 8 * DMODEL) = make_float2(c2, c3);
        }
    }
}

// ---------------- attention role (bf16 path unchanged + exact skips) -------
#define ASA 72
#define STG (256 * ASA)

__device__ __forceinline__ void attn_work(char* sbuf, int b, int h, int qt)
{
    __nv_bfloat16* sm = (__nv_bfloat16*)sbuf;   // 2 * STG elems = 73,728 B

    const int tid  = threadIdx.x;
    const int lane = tid & 31;
    const int w    = tid >> 5;
    const int bh   = b * NHEADS + h;
    const int q0   = qt * 128;

    const __nv_bfloat16* Qh = g_qh + (size_t)bh * SEQ * DK;
    const __nv_bfloat16* Ql = g_ql + (size_t)bh * SEQ * DK;
    const __nv_bfloat16* Kh = g_kh + (size_t)bh * SEQ * DK;
    const __nv_bfloat16* Kl = g_kl + (size_t)bh * SEQ * DK;
    const __nv_bfloat16* Vh = g_vh + (size_t)bh * SEQ * DK;
    const __nv_bfloat16* Vl = g_vl + (size_t)bh * SEQ * DK;

    const uint32_t sb = smem_u32(sm);
    const int sub = lane >> 3, l7 = lane & 7;

    uint32_t qfh[4][4], qfl[4][4];
    {
#pragma unroll
        for (int v = 0; v < 4; v++) {
            const int item = v * 256 + tid;
            const int row = item >> 3, sec = item & 7;
            const size_t gi = (size_t)(q0 + row) * DK + sec * 8;
            *(uint4*)(sm + STG + row * ASA + sec * 8)             = *(const uint4*)(Qh + gi);
            *(uint4*)(sm + STG + 128 * ASA + row * ASA + sec * 8) = *(const uint4*)(Ql + gi);
        }
        __syncthreads();
        const int arow = w * 16 + l7 + (sub & 1) * 8;
        const int akof = (sub >> 1) * 8;
#pragma unroll
        for (int ks = 0; ks < 4; ks++) {
            const uint32_t off = (uint32_t)(STG + arow * ASA + ks * 16 + akof) * 2;
            ldsm_x4(qfh[ks][0], qfh[ks][1], qfh[ks][2], qfh[ks][3], sb + off);
            ldsm_x4(qfl[ks][0], qfl[ks][1], qfl[ks][2], qfl[ks][3], sb + (uint32_t)(128 * ASA) * 2 + off);
        }
    }

    float o[8][4];
#pragma unroll
    for (int nt = 0; nt < 8; nt++)
#pragma unroll
        for (int c = 0; c < 4; c++) o[nt][c] = 0.0f;
    float m0r = -1e30f, m1r = -1e30f, l0r = 0.0f, l1r = 0.0f;

    const int g     = lane >> 2;
    const int r0    = q0 + w * 16 + g;
    const int cpair = (lane & 3) * 2;
    const int rmax  = q0 + w * 16 + 15;

    const int ntiles = qt * 2 + 2;
    const int grow = tid >> 3, gsec = tid & 7;

#pragma unroll
    for (int v = 0; v < 2; v++) {
        const int row = v * 32 + grow, sec = gsec;
        const size_t gi = (size_t)row * DK + sec * 8;
        const int so = row * ASA + sec * 8;
        *(uint4*)(sm + so)             = *(const uint4*)(Kh + gi);
        *(uint4*)(sm + 64 * ASA + so)  = *(const uint4*)(Kl + gi);
        *(uint4*)(sm + 128 * ASA + so) = *(const uint4*)(Vh + gi);
        *(uint4*)(sm + 192 * ASA + so) = *(const uint4*)(Vl + gi);
    }
    uint4 va[2][4];
    if (ntiles > 1) {
#pragma unroll
        for (int v = 0; v < 2; v++) {
            const int row = v * 32 + grow;
            const size_t gi = (size_t)(64 + row) * DK + gsec * 8;
            va[v][0] = *(const uint4*)(Kh + gi);
            va[v][1] = *(const uint4*)(Kl + gi);
            va[v][2] = *(const uint4*)(Vh + gi);
            va[v][3] = *(const uint4*)(Vl + gi);
        }
    }
    __syncthreads();

    const float sc2 = 0.18033688011f;   // 0.125 * log2(e)

    for (int kt = 0; kt < ntiles; kt++) {
        const int k0 = kt * 64;
        const uint32_t cb = sb + (uint32_t)((kt & 1) * STG) * 2;

        if (kt + 1 < ntiles) {
            __nv_bfloat16* nx = sm + ((kt + 1) & 1) * STG;
#pragma unroll
            for (int v = 0; v < 2; v++) {
                const int row = v * 32 + grow;
                const int so = row * ASA + gsec * 8;
                *(uint4*)(nx + so)             = va[v][0];
                *(uint4*)(nx + 64 * ASA + so)  = va[v][1];
                *(uint4*)(nx + 128 * ASA + so) = va[v][2];
                *(uint4*)(nx + 192 * ASA + so) = va[v][3];
            }
            if (kt + 2 < ntiles) {
                const int nk0 = k0 + 128;
#pragma unroll
                for (int v = 0; v < 2; v++) {
                    const int row = v * 32 + grow;
                    const size_t gi = (size_t)(nk0 + row) * DK + gsec * 8;
                    va[v][0] = *(const uint4*)(Kh + gi);
                    va[v][1] = *(const uint4*)(Kl + gi);
                    va[v][2] = *(const uint4*)(Vh + gi);
                    va[v][3] = *(const uint4*)(Vl + gi);
                }
            }
        }

        if (k0 <= rmax) {
            const int nt_lim = (rmax - k0) >> 3;   // fully-masked n-tiles skipped (exact)
            float d[8][4];
#pragma unroll
            for (int nt = 0; nt < 8; nt++)
#pragma unroll
                for (int c = 0; c < 4; c++) d[nt][c] = 0.0f;

            const int brow = l7 + (sub >> 1) * 8;
            const int bkof = (sub & 1) * 8;
#pragma unroll
            for (int ks = 0; ks < 4; ks++) {
                uint32_t fh[8][2], fl[8][2];
#pragma unroll
                for (int g2 = 0; g2 < 4; g2++) {
                    const uint32_t off = (uint32_t)((g2 * 16 + brow) * ASA + ks * 16 + bkof) * 2;
                    ldsm_x4(fh[2 * g2][0], fh[2 * g2][1], fh[2 * g2 + 1][0], fh[2 * g2 + 1][1], cb + off);
                    ldsm_x4(fl[2 * g2][0], fl[2 * g2][1], fl[2 * g2 + 1][0], fl[2 * g2 + 1][1], cb + (uint32_t)(64 * ASA) * 2 + off);
                }
#pragma unroll
                for (int nt = 0; nt < 8; nt++) {
                    if (nt <= nt_lim) {
                        mma16816(d[nt], qfh[ks], fh[nt]);
                        mma16816(d[nt], qfh[ks], fl[nt]);
                        mma16816(d[nt], qfl[ks], fh[nt]);
                    }
                }
            }

            const bool need_mask = (k0 + 63 > q0 + w * 16);
#pragma unroll
            for (int nt = 0; nt < 8; nt++) {
                const int key0 = k0 + nt * 8 + cpair;
                float v0 = d[nt][0] * sc2, v1 = d[nt][1] * sc2;
                float v2 = d[nt][2] * sc2, v3 = d[nt][3] * sc2;
                if (need_mask) {
                    if (key0     > r0)     v0 = -1e30f;
                    if (key0 + 1 > r0)     v1 = -1e30f;
                    if (key0     > r0 + 8) v2 = -1e30f;
                    if (key0 + 1 > r0 + 8) v3 = -1e30f;
                }
                d[nt][0] = v0; d[nt][1] = v1; d[nt][2] = v2; d[nt][3] = v3;
            }

            float mx0 = -1e30f, mx1 = -1e30f;
#pragma unroll
            for (int nt = 0; nt < 8; nt++) {
                mx0 = fmaxf(mx0, fmaxf(d[nt][0], d[nt][1]));
                mx1 = fmaxf(mx1, fmaxf(d[nt][2], d[nt][3]));
            }
            mx0 = fmaxf(mx0, __shfl_xor_sync(0xffffffffu, mx0, 1));
            mx0 = fmaxf(mx0, __shfl_xor_sync(0xffffffffu, mx0, 2));
            mx1 = fmaxf(mx1, __shfl_xor_sync(0xffffffffu, mx1, 1));
            mx1 = fmaxf(mx1, __shfl_xor_sync(0xffffffffu, mx1, 2));

            const float mn0 = fmaxf(m0r, mx0);
            const float mn1 = fmaxf(m1r, mx1);
            const float a0 = ex2f(m0r - mn0);
            const float a1 = ex2f(m1r - mn1);
            m0r = mn0; m1r = mn1;

            float rs0 = 0.0f, rs1 = 0.0f;
#pragma unroll
            for (int nt = 0; nt < 8; nt++) {
                d[nt][0] = ex2f(d[nt][0] - mn0);
                d[nt][1] = ex2f(d[nt][1] - mn0);
                d[nt][2] = ex2f(d[nt][2] - mn1);
                d[nt][3] = ex2f(d[nt][3] - mn1);
                rs0 += d[nt][0] + d[nt][1];
                rs1 += d[nt][2] + d[nt][3];
            }
            rs0 += __shfl_xor_sync(0xffffffffu, rs0, 1);
            rs0 += __shfl_xor_sync(0xffffffffu, rs0, 2);
            rs1 += __shfl_xor_sync(0xffffffffu, rs1, 1);
            rs1 += __shfl_xor_sync(0xffffffffu, rs1, 2);
            l0r = l0r * a0 + rs0;
            l1r = l1r * a1 + rs1;

#pragma unroll
            for (int nt = 0; nt < 8; nt++) {
                o[nt][0] *= a0; o[nt][1] *= a0;
                o[nt][2] *= a1; o[nt][3] *= a1;
            }

#pragma unroll
            for (int kst = 0; kst < 4; kst++) {
                if (k0 + kst * 16 <= rmax) {       // P == 0 exactly beyond rmax
                    uint32_t pah[4], pal[4];
                    split2(d[2 * kst][0],     d[2 * kst][1],     pah[0], pal[0]);
                    split2(d[2 * kst][2],     d[2 * kst][3],     pah[1], pal[1]);
                    split2(d[2 * kst + 1][0], d[2 * kst + 1][1], pah[2], pal[2]);
                    split2(d[2 * kst + 1][2], d[2 * kst + 1][3], pah[3], pal[3]);
                    const int vrow = kst * 16 + l7 + (sub & 1) * 8;
                    const int vkof = (sub >> 1) * 8;
#pragma unroll
                    for (int g2 = 0; g2 < 4; g2++) {
                        uint32_t vh[4], vl[4];
                        const uint32_t off = (uint32_t)(vrow * ASA + g2 * 16 + vkof) * 2;
                        ldsm_x4t(vh[0], vh[1], vh[2], vh[3], cb + (uint32_t)(128 * ASA) * 2 + off);
                        ldsm_x4t(vl[0], vl[1], vl[2], vl[3], cb + (uint32_t)(192 * ASA) * 2 + off);
                        mma16816(o[2 * g2],     pah, &vh[0]);
                        mma16816(o[2 * g2],     pah, &vl[0]);
                        mma16816(o[2 * g2],     pal, &vh[0]);
                        mma16816(o[2 * g2 + 1], pah, &vh[2]);
                        mma16816(o[2 * g2 + 1], pah, &vl[2]);
                        mma16816(o[2 * g2 + 1], pal, &vh[2]);
                    }
                }
            }
        }
        __syncthreads();
    }

    // epilogue: normalize -> fp32 g_O (concat [m,d])
    const float i0 = 1.0f / l0r;
    const float i1 = 1.0f / l1r;
#pragma unroll
    for (int nt = 0; nt < 8; nt++) {
        const int dkc = h * 64 + nt * 8 + cpair;
        const size_t idx = ((size_t)b * SEQ + r0) * DMODEL + dkc;
        *(float2*)(g_O + idx)               = make_float2(o[nt][0] * i0, o[nt][1] * i0);
        *(float2*)(g_O + idx + 8 * DMODEL)  = make_float2(o[nt][2] * i1, o[nt][3] * i1);
    }
}

// ---------------- cvt-O role: slice fp32 O rows into int8 -------------------
__device__ __forceinline__ void cvtO_work(int mb)
{
    const int tid = threadIdx.x;
    const int wid = tid >> 5, lane = tid & 31;
    const int m0 = mb * 128;
#pragma unroll 1
    for (int rr = 0; rr < 16; rr++) {
        const int row = m0 + wid * 16 + rr;
        const float4* src = (const float4*)(g_O + (size_t)row * DMODEL);
        float4 v[8];
        float mx = 0.0f;
#pragma unroll
        for (int i = 0; i < 8; i++) {
            v[i] = src[i * 32 + lane];
            mx = fmaxf(mx, fmaxf(fmaxf(fabsf(v[i].x), fabsf(v[i].y)),
                                 fmaxf(fabsf(v[i].z), fabsf(v[i].w))));
        }
#pragma unroll
        for (int s = 16; s > 0; s >>= 1)
            mx = fmaxf(mx, __shfl_xor_sync(0xffffffffu, mx, s));
        const float inv = 127.0f / fmaxf(mx, 1e-30f);
        if (lane == 0) g_sO[row] = mx * (1.0f / 127.0f);
#pragma unroll
        for (int i = 0; i < 8; i++) {
            uint32_t u1, u2;
            q2pack((const float*)&v[i], inv, u1, u2);
            ((uint32_t*)(g_O1 + (size_t)row * DMODEL))[i * 32 + lane] = u1;
            ((uint32_t*)(g_O2 + (size_t)row * DMODEL))[i * 32 + lane] = u2;
        }
    }
}

// ===========================================================================
// Mega-kernel: bid [0,768) qkv | [768,1280) attn | [1280,1312) cvt-O |
// [1312,1568) out. Producers precede consumers in bid order (no deadlock).
// ===========================================================================
#define MEGA_SMEM (2 * STG * 2)   // 73,728 B (attn is the max user)

__global__ __launch_bounds__(256) void mega_kernel(
    const float* __restrict__ bias, float* __restrict__ out)
{
    extern __shared__ char sbuf[];
    const int bid = blockIdx.x;
    const int tid = threadIdx.x;

    if (bid < 768) {
        const int nx  = bid / 96;
        const int rem = bid - nx * 96;
        const int my  = rem / 3;
        const int z   = rem - my * 3;
        qkv_work(sbuf, z, my * 128, nx * 128);
        __threadfence();
        __syncthreads();
        if (tid == 0) atomicAdd(&g_cntPair[nx], 1);
    } else if (bid < 1280) {
        const int abid = bid - 768;
        const int pair = abid >> 6;
        const int w64  = abid & 63;
        const int qt   = 15 - (w64 >> 2);
        const int bs   = w64 & 3;
        const int b    = bs >> 1;
        const int h    = pair * 2 + (bs & 1);
        if (tid == 0) { while (ld_acq(&g_cntPair[pair]) < 96) { } }
        __syncthreads();
        attn_work(sbuf, b, h, qt);
        __threadfence();
        __syncthreads();
        if (tid == 0) atomicAdd(&g_cntO[b * 16 + qt], 1);
    } else if (bid < 1312) {
        const int mb = bid - 1280;
        if (tid == 0) { while (ld_acq(&g_cntO[mb]) < 16) { } }
        __syncthreads();
        cvtO_work(mb);
        __threadfence();
        __syncthreads();
        if (tid == 0) atomicAdd(&g_cntQO[mb], 1);
    } else {
        const int obid = bid - 1312;
        const int mb   = obid >> 3;
        const int nbx  = obid & 7;
        if (tid == 0) { while (ld_acq(&g_cntQO[mb]) < 1) { } }
        __syncthreads();
        out_work(sbuf, mb * 128, nbx * 128, bias, out);
    }
}

// ===========================================================================
extern "C" void kernel_launch(void* const* d_in, const int* in_sizes, int n_in,
                              void* d_out, int out_size)
{
    (void)in_sizes; (void)n_in; (void)out_size;
    const float* x  = (const float*)d_in[0];
    const float* Wq = (const float*)d_in[1];
    const float* Wk = (const float*)d_in[2];
    const float* Wv = (const float*)d_in[3];
    const float* Wo = (const float*)d_in[4];
    const float* bo = (const float*)d_in[5];
    float* out = (float*)d_out;

    cudaFuncSetAttribute(mega_kernel,
                         cudaFuncAttributeMaxDynamicSharedMemorySize, MEGA_SMEM);

    cvt_s8_kernel<<<1024, 256>>>(x, Wq, Wk, Wv, Wo);   // 8192 rows, 1 warp/row
    mega_kernel<<<1568, 256, MEGA_SMEM>>>(bo, out);
}

// round 14
// speedup vs baseline: 1.6213x; 1.6213x over previous
#include <cuda_runtime.h>
#include <cuda_fp16.h>
#include <math.h>
#include <stdint.h>

#define BATCH   2
#define SEQ     2048
#define DMODEL  1024
#define NHEADS  16
#define DK      64
#define MROWS   (BATCH * SEQ)   // 4096

// -------------------- scratch (__device__ globals; no allocations) ---------
__device__ __half g_Xh[(size_t)MROWS * DMODEL];
__device__ __half g_Xl[(size_t)MROWS * DMODEL];
__device__ __half g_Wh[4][(size_t)DMODEL * DMODEL];  // q,k,v,o
__device__ __half g_Wl[4][(size_t)DMODEL * DMODEL];
__device__ __half g_qh[(size_t)BATCH * NHEADS * SEQ * DK];
__device__ __half g_ql[(size_t)BATCH * NHEADS * SEQ * DK];
__device__ __half g_kh[(size_t)BATCH * NHEADS * SEQ * DK];
__device__ __half g_kl[(size_t)BATCH * NHEADS * SEQ * DK];
__device__ __half g_vh[(size_t)BATCH * NHEADS * SEQ * DK];
__device__ __half g_vl[(size_t)BATCH * NHEADS * SEQ * DK];
__device__ __half g_Oh[(size_t)MROWS * DMODEL];
__device__ __half g_Ol[(size_t)MROWS * DMODEL];

// readiness counters (zeroed by cvt_all_kernel every call)
__device__ int g_cntPair[8];   // qkv CTAs done per head-pair (target 96)
__device__ int g_cntO[32];     // attn CTAs done per (b,qt) m-block (target 16)

// ===========================================================================
// warp-MMA helpers
// ===========================================================================
__device__ __forceinline__ uint32_t smem_u32(const void* p) {
    uint32_t a;
    asm("{ .reg .u64 t; cvta.to.shared.u64 t, %1; cvt.u32.u64 %0, t; }"
        : "=r"(a) : "l"(p));
    return a;
}

__device__ __forceinline__ void ldsm_x4(uint32_t& r0, uint32_t& r1,
                                        uint32_t& r2, uint32_t& r3, uint32_t addr) {
    asm volatile("ldmatrix.sync.aligned.m8n8.x4.shared.b16 {%0,%1,%2,%3}, [%4];"
                 : "=r"(r0), "=r"(r1), "=r"(r2), "=r"(r3) : "r"(addr));
}

__device__ __forceinline__ void ldsm_x4t(uint32_t& r0, uint32_t& r1,
                                         uint32_t& r2, uint32_t& r3, uint32_t addr) {
    asm volatile("ldmatrix.sync.aligned.m8n8.x4.trans.shared.b16 {%0,%1,%2,%3}, [%4];"
                 : "=r"(r0), "=r"(r1), "=r"(r2), "=r"(r3) : "r"(addr));
}

// f16 inputs, fp32 accumulator (main hh pass)
__device__ __forceinline__ void mma_f32(float* d, const uint32_t* a, const uint32_t* b) {
    asm volatile(
        "mma.sync.aligned.m16n8k16.row.col.f32.f16.f16.f32 "
        "{%0,%1,%2,%3}, {%4,%5,%6,%7}, {%8,%9}, {%0,%1,%2,%3};"
        : "+f"(d[0]), "+f"(d[1]), "+f"(d[2]), "+f"(d[3])
        : "r"(a[0]), "r"(a[1]), "r"(a[2]), "r"(a[3]), "r"(b[0]), "r"(b[1]));
}

// f16 inputs, f16 accumulator (correction passes; D = 2 packed regs)
__device__ __forceinline__ void mma_f16(uint32_t* d, const uint32_t* a, const uint32_t* b) {
    asm volatile(
        "mma.sync.aligned.m16n8k16.row.col.f16.f16.f16.f16 "
        "{%0,%1}, {%2,%3,%4,%5}, {%6,%7}, {%0,%1};"
        : "+r"(d[0]), "+r"(d[1])
        : "r"(a[0]), "r"(a[1]), "r"(a[2]), "r"(a[3]), "r"(b[0]), "r"(b[1]));
}

__device__ __forceinline__ float2 h2f(uint32_t u) {
    __half2 h = *(__half2*)&u;
    return __half22float2(h);
}

__device__ __forceinline__ float ex2f(float x) {
    float r;
    asm("ex2.approx.f32 %0, %1;" : "=f"(r) : "f"(x));
    return r;
}

// split pair of fp32 -> packed f16x2 hi + packed f16x2 lo residual
__device__ __forceinline__ void split2(float x, float y, uint32_t& hi, uint32_t& lo) {
    uint32_t h;
    asm("cvt.rn.f16x2.f32 %0, %1, %2;" : "=r"(h) : "f"(y), "f"(x));  // lo16=x, hi16=y
    __half2 hh = *(__half2*)&h;
    const float rx = x - __half2float(__low2half(hh));
    const float ry = y - __half2float(__high2half(hh));
    uint32_t l;
    asm("cvt.rn.f16x2.f32 %0, %1, %2;" : "=r"(l) : "f"(ry), "f"(rx));
    hi = h; lo = l;
}

__device__ __forceinline__ int ld_acq(const int* p) {
    int v;
    asm volatile("ld.acquire.gpu.b32 %0, [%1];" : "=r"(v) : "l"(p) : "memory");
    return v;
}

// ===========================================================================
// merged fp32 -> (hi, lo) fp16 split for X + 4 W's; zeroes sync counters
// ===========================================================================
#define NX4 (MROWS * DMODEL / 4)     // 1,048,576
#define NW4 (DMODEL * DMODEL / 4)    //   262,144

__global__ void cvt_all_kernel(const float* __restrict__ x,
                               const float* __restrict__ wq,
                               const float* __restrict__ wk,
                               const float* __restrict__ wv,
                               const float* __restrict__ wo)
{
    if (blockIdx.x == 0 && threadIdx.x < 40) {
        if (threadIdx.x < 8) g_cntPair[threadIdx.x] = 0;
        else                 g_cntO[threadIdx.x - 8] = 0;
    }
    const int i = blockIdx.x * blockDim.x + threadIdx.x;
    const float* src;
    __half *hi, *lo;
    int idx;
    if (i < NX4) { src = x; hi = g_Xh; lo = g_Xl; idx = i; }
    else {
        const int j = i - NX4;
        const int wsel = j / NW4;
        idx = j - wsel * NW4;
        src = (wsel == 0) ? wq : (wsel == 1) ? wk : (wsel == 2) ? wv : wo;
        hi = g_Wh[wsel]; lo = g_Wl[wsel];
    }
    float4 v = ((const float4*)src)[idx];
    uint32_t h0, h1, l0, l1;
    split2(v.x, v.y, h0, l0);
    split2(v.z, v.w, h1, l1);
    ((uint2*)hi)[idx] = make_uint2(h0, h1);
    ((uint2*)lo)[idx] = make_uint2(l0, l1);
}

// ===========================================================================
// Split-fp16 GEMM core: hh -> f32 accum; (hl + lh) -> f16 accum, merged once.
// ===========================================================================
#define SA 40

__device__ __forceinline__ void gemm_tile_core(
    const __half* __restrict__ Ah, const __half* __restrict__ Al,
    const __half* __restrict__ Bh, const __half* __restrict__ Bl,
    int m0, int n0, float d[2][8][4], char* sbuf)
{
    __half* sAh = (__half*)sbuf;
    __half* sAl = sAh + 128 * SA;
    __half* sBh = sAl + 128 * SA;
    __half* sBl = sBh + 128 * SA;

    const int tid  = threadIdx.x;
    const int lane = tid & 31;
    const int wid  = tid >> 5;
    const int wm   = wid >> 1;
    const int wn   = wid & 1;

    const uint32_t aAh = smem_u32(sAh), aAl = smem_u32(sAl);
    const uint32_t aBh = smem_u32(sBh), aBl = smem_u32(sBl);

    const int sub  = lane >> 3, l7 = lane & 7;
    const int arow = wm * 32 + l7 + (sub & 1) * 8;
    const int akof = (sub >> 1) * 8;
    const int brow = wn * 64 + l7 + (sub >> 1) * 8;
    const int bkof = (sub & 1) * 8;

    const int grow = tid >> 2;
    const int gq   = (tid & 3) * 8;

    uint32_t dc[2][8][2];    // f16-accum corrections (hl + lh)
#pragma unroll
    for (int mt = 0; mt < 2; mt++)
#pragma unroll
        for (int nt = 0; nt < 8; nt++) {
#pragma unroll
            for (int c = 0; c < 4; c++) d[mt][nt][c] = 0.0f;
            dc[mt][nt][0] = 0u; dc[mt][nt][1] = 0u;
        }

    uint4 va[2][4];
#pragma unroll
    for (int p = 0; p < 2; p++) {
        const size_t ga = (size_t)(m0 + p * 64 + grow) * DMODEL + gq;
        const size_t gb = (size_t)(n0 + p * 64 + grow) * DMODEL + gq;
        va[p][0] = *(const uint4*)(Ah + ga);
        va[p][1] = *(const uint4*)(Al + ga);
        va[p][2] = *(const uint4*)(Bh + gb);
        va[p][3] = *(const uint4*)(Bl + gb);
    }

    for (int it = 0; it < DMODEL / 32; it++) {
        __syncthreads();
#pragma unroll
        for (int p = 0; p < 2; p++) {
            const int so = (p * 64 + grow) * SA + gq;
            *(uint4*)(sAh + so) = va[p][0];
            *(uint4*)(sAl + so) = va[p][1];
            *(uint4*)(sBh + so) = va[p][2];
            *(uint4*)(sBl + so) = va[p][3];
        }
        if (it + 1 < DMODEL / 32) {
            const int k0 = (it + 1) * 32;
#pragma unroll
            for (int p = 0; p < 2; p++) {
                const size_t ga = (size_t)(m0 + p * 64 + grow) * DMODEL + k0 + gq;
                const size_t gb = (size_t)(n0 + p * 64 + grow) * DMODEL + k0 + gq;
                va[p][0] = *(const uint4*)(Ah + ga);
                va[p][1] = *(const uint4*)(Al + ga);
                va[p][2] = *(const uint4*)(Bh + gb);
                va[p][3] = *(const uint4*)(Bl + gb);
            }
        }
        __syncthreads();

#pragma unroll
        for (int s = 0; s < 2; s++) {
            const int ks = s * 16;
            uint32_t fAh[2][4], fAl[2][4], fBh[8][2], fBl[8][2];
#pragma unroll
            for (int mt = 0; mt < 2; mt++) {
                const uint32_t off = ((arow + mt * 16) * SA + ks + akof) * 2;
                ldsm_x4(fAh[mt][0], fAh[mt][1], fAh[mt][2], fAh[mt][3], aAh + off);
                ldsm_x4(fAl[mt][0], fAl[mt][1], fAl[mt][2], fAl[mt][3], aAl + off);
            }
#pragma unroll
            for (int g = 0; g < 4; g++) {
                const uint32_t off = ((brow + g * 16) * SA + ks + bkof) * 2;
                ldsm_x4(fBh[2 * g][0], fBh[2 * g][1], fBh[2 * g + 1][0], fBh[2 * g + 1][1], aBh + off);
                ldsm_x4(fBl[2 * g][0], fBl[2 * g][1], fBl[2 * g + 1][0], fBl[2 * g + 1][1], aBl + off);
            }
#pragma unroll
            for (int mt = 0; mt < 2; mt++)
#pragma unroll
                for (int nt = 0; nt < 8; nt++) {
                    mma_f32(d[mt][nt], fAh[mt], fBh[nt]);
                    mma_f16(dc[mt][nt], fAh[mt], fBl[nt]);
                    mma_f16(dc[mt][nt], fAl[mt], fBh[nt]);
                }
        }
    }

    // fold f16-accum corrections into the fp32 accumulators
#pragma unroll
    for (int mt = 0; mt < 2; mt++)
#pragma unroll
        for (int nt = 0; nt < 8; nt++) {
            const float2 c01 = h2f(dc[mt][nt][0]);
            const float2 c23 = h2f(dc[mt][nt][1]);
            d[mt][nt][0] += c01.x; d[mt][nt][1] += c01.y;
            d[mt][nt][2] += c23.x; d[mt][nt][3] += c23.y;
        }
}

// ---------------- qkv role body -------------------------------------------
__device__ __forceinline__ void qkv_work(char* sbuf, int z, int m0, int n0)
{
    float d[2][8][4];
    gemm_tile_core(g_Xh, g_Xl, g_Wh[z], g_Wl[z], m0, n0, d, sbuf);

    __half* dh = (z == 0) ? g_qh : (z == 1 ? g_kh : g_vh);
    __half* dl = (z == 0) ? g_ql : (z == 1 ? g_kl : g_vl);
    const int lane = threadIdx.x & 31, wid = threadIdx.x >> 5;
    const int wm = wid >> 1, wn = wid & 1;
#pragma unroll
    for (int mt = 0; mt < 2; mt++) {
        const int r0 = m0 + wm * 32 + mt * 16 + (lane >> 2);
        const int b = r0 >> 11;
        const int s = r0 & (SEQ - 1);
#pragma unroll
        for (int nt = 0; nt < 8; nt++) {
            const int e  = n0 + wn * 64 + nt * 8 + (lane & 3) * 2;
            const int h  = e >> 6, dk = e & 63;
            const size_t i0 = (((size_t)b * NHEADS + h) * SEQ + s) * DK + dk;
            uint32_t hi, lo;
            split2(d[mt][nt][0], d[mt][nt][1], hi, lo);
            *(uint32_t*)(dh + i0) = hi;
            *(uint32_t*)(dl + i0) = lo;
            split2(d[mt][nt][2], d[mt][nt][3], hi, lo);
            *(uint32_t*)(dh + i0 + 8 * DK) = hi;
            *(uint32_t*)(dl + i0 + 8 * DK) = lo;
        }
    }
}

// ---------------- out-proj role body --------------------------------------
__device__ __forceinline__ void out_work(char* sbuf, int m0, int n0,
                                         const float* __restrict__ bias,
                                         float* __restrict__ out)
{
    float d[2][8][4];
    gemm_tile_core(g_Oh, g_Ol, g_Wh[3], g_Wl[3], m0, n0, d, sbuf);

    const int lane = threadIdx.x & 31, wid = threadIdx.x >> 5;
    const int wm = wid >> 1, wn = wid & 1;
#pragma unroll
    for (int mt = 0; mt < 2; mt++) {
        const int r0 = m0 + wm * 32 + mt * 16 + (lane >> 2);
#pragma unroll
        for (int nt = 0; nt < 8; nt++) {
            const int e = n0 + wn * 64 + nt * 8 + (lane & 3) * 2;
            const float b0 = bias[e], b1 = bias[e + 1];
            float* p0 = out + (size_t)r0 * DMODEL + e;
            *(float2*)p0                 = make_float2(d[mt][nt][0] + b0, d[mt][nt][1] + b1);
            *(float2*)(p0 + 8 * DMODEL)  = make_float2(d[mt][nt][2] + b0, d[mt][nt][3] + b1);
        }
    }
}

// ---------------- attention role body -------------------------------------
#define ASA 72
#define STG (256 * ASA)

__device__ __forceinline__ void attn_work(char* sbuf, int b, int h, int qt)
{
    __half* sm = (__half*)sbuf;   // 2 * STG elems = 73,728 B

    const int tid  = threadIdx.x;
    const int lane = tid & 31;
    const int w    = tid >> 5;
    const int bh   = b * NHEADS + h;
    const int q0   = qt * 128;

    const __half* Qh = g_qh + (size_t)bh * SEQ * DK;
    const __half* Ql = g_ql + (size_t)bh * SEQ * DK;
    const __half* Kh = g_kh + (size_t)bh * SEQ * DK;
    const __half* Kl = g_kl + (size_t)bh * SEQ * DK;
    const __half* Vh = g_vh + (size_t)bh * SEQ * DK;
    const __half* Vl = g_vl + (size_t)bh * SEQ * DK;

    const uint32_t sb = smem_u32(sm);
    const int sub = lane >> 3, l7 = lane & 7;

    // ---- prologue: Q staged in stage-1 area, fragments to registers -------
    uint32_t qfh[4][4], qfl[4][4];
    {
#pragma unroll
        for (int v = 0; v < 4; v++) {
            const int item = v * 256 + tid;
            const int row = item >> 3, sec = item & 7;
            const size_t gi = (size_t)(q0 + row) * DK + sec * 8;
            *(uint4*)(sm + STG + row * ASA + sec * 8)             = *(const uint4*)(Qh + gi);
            *(uint4*)(sm + STG + 128 * ASA + row * ASA + sec * 8) = *(const uint4*)(Ql + gi);
        }
        __syncthreads();
        const int arow = w * 16 + l7 + (sub & 1) * 8;
        const int akof = (sub >> 1) * 8;
#pragma unroll
        for (int ks = 0; ks < 4; ks++) {
            const uint32_t off = (uint32_t)(STG + arow * ASA + ks * 16 + akof) * 2;
            ldsm_x4(qfh[ks][0], qfh[ks][1], qfh[ks][2], qfh[ks][3], sb + off);
            ldsm_x4(qfl[ks][0], qfl[ks][1], qfl[ks][2], qfl[ks][3], sb + (uint32_t)(128 * ASA) * 2 + off);
        }
    }

    float o[8][4];
#pragma unroll
    for (int nt = 0; nt < 8; nt++)
#pragma unroll
        for (int c = 0; c < 4; c++) o[nt][c] = 0.0f;
    float m0r = -1e30f, m1r = -1e30f, l0r = 0.0f, l1r = 0.0f;

    const int g     = lane >> 2;
    const int r0    = q0 + w * 16 + g;
    const int cpair = (lane & 3) * 2;
    const int rmax  = q0 + w * 16 + 15;

    const int ntiles = qt * 2 + 2;
    const int grow = tid >> 3, gsec = tid & 7;

    // tile 0 direct to stage 0
#pragma unroll
    for (int v = 0; v < 2; v++) {
        const int row = v * 32 + grow, sec = gsec;
        const size_t gi = (size_t)row * DK + sec * 8;
        const int so = row * ASA + sec * 8;
        *(uint4*)(sm + so)             = *(const uint4*)(Kh + gi);
        *(uint4*)(sm + 64 * ASA + so)  = *(const uint4*)(Kl + gi);
        *(uint4*)(sm + 128 * ASA + so) = *(const uint4*)(Vh + gi);
        *(uint4*)(sm + 192 * ASA + so) = *(const uint4*)(Vl + gi);
    }
    uint4 va[2][4];
    if (ntiles > 1) {
#pragma unroll
        for (int v = 0; v < 2; v++) {
            const int row = v * 32 + grow;
            const size_t gi = (size_t)(64 + row) * DK + gsec * 8;
            va[v][0] = *(const uint4*)(Kh + gi);
            va[v][1] = *(const uint4*)(Kl + gi);
            va[v][2] = *(const uint4*)(Vh + gi);
            va[v][3] = *(const uint4*)(Vl + gi);
        }
    }
    __syncthreads();

    const float sc2 = 0.18033688011f;   // 0.125 * log2(e)

    for (int kt = 0; kt < ntiles; kt++) {
        const int k0 = kt * 64;
        const uint32_t cb = sb + (uint32_t)((kt & 1) * STG) * 2;

        if (kt + 1 < ntiles) {
            __half* nx = sm + ((kt + 1) & 1) * STG;
#pragma unroll
            for (int v = 0; v < 2; v++) {
                const int row = v * 32 + grow;
                const int so = row * ASA + gsec * 8;
                *(uint4*)(nx + so)             = va[v][0];
                *(uint4*)(nx + 64 * ASA + so)  = va[v][1];
                *(uint4*)(nx + 128 * ASA + so) = va[v][2];
                *(uint4*)(nx + 192 * ASA + so) = va[v][3];
            }
            if (kt + 2 < ntiles) {
                const int nk0 = k0 + 128;
#pragma unroll
                for (int v = 0; v < 2; v++) {
                    const int row = v * 32 + grow;
                    const size_t gi = (size_t)(nk0 + row) * DK + gsec * 8;
                    va[v][0] = *(const uint4*)(Kh + gi);
                    va[v][1] = *(const uint4*)(Kl + gi);
                    va[v][2] = *(const uint4*)(Vh + gi);
                    va[v][3] = *(const uint4*)(Vl + gi);
                }
            }
        }

        if (k0 <= rmax) {
            const int nt_lim = (rmax - k0) >> 3;   // exact skip of fully-masked n-tiles
            // ---- S = Q K^T -----------------------------------------------
            float d[8][4];
            uint32_t sc[8][2];
#pragma unroll
            for (int nt = 0; nt < 8; nt++) {
#pragma unroll
                for (int c = 0; c < 4; c++) d[nt][c] = 0.0f;
                sc[nt][0] = 0u; sc[nt][1] = 0u;
            }

            const int brow = l7 + (sub >> 1) * 8;
            const int bkof = (sub & 1) * 8;
#pragma unroll
            for (int ks = 0; ks < 4; ks++) {
                uint32_t fh[8][2], fl[8][2];
#pragma unroll
                for (int g2 = 0; g2 < 4; g2++) {
                    const uint32_t off = (uint32_t)((g2 * 16 + brow) * ASA + ks * 16 + bkof) * 2;
                    ldsm_x4(fh[2 * g2][0], fh[2 * g2][1], fh[2 * g2 + 1][0], fh[2 * g2 + 1][1], cb + off);
                    ldsm_x4(fl[2 * g2][0], fl[2 * g2][1], fl[2 * g2 + 1][0], fl[2 * g2 + 1][1], cb + (uint32_t)(64 * ASA) * 2 + off);
                }
#pragma unroll
                for (int nt = 0; nt < 8; nt++) {
                    if (nt <= nt_lim) {
                        mma_f32(d[nt], qfh[ks], fh[nt]);
                        mma_f16(sc[nt], qfh[ks], fl[nt]);
                        mma_f16(sc[nt], qfl[ks], fh[nt]);
                    }
                }
            }
#pragma unroll
            for (int nt = 0; nt < 8; nt++) {
                const float2 c01 = h2f(sc[nt][0]);
                const float2 c23 = h2f(sc[nt][1]);
                d[nt][0] += c01.x; d[nt][1] += c01.y;
                d[nt][2] += c23.x; d[nt][3] += c23.y;
            }

            // ---- scale (base-2) + causal mask ----------------------------
            const bool need_mask = (k0 + 63 > q0 + w * 16);
#pragma unroll
            for (int nt = 0; nt < 8; nt++) {
                const int key0 = k0 + nt * 8 + cpair;
                float v0 = d[nt][0] * sc2, v1 = d[nt][1] * sc2;
                float v2 = d[nt][2] * sc2, v3 = d[nt][3] * sc2;
                if (need_mask) {
                    if (key0     > r0)     v0 = -1e30f;
                    if (key0 + 1 > r0)     v1 = -1e30f;
                    if (key0     > r0 + 8) v2 = -1e30f;
                    if (key0 + 1 > r0 + 8) v3 = -1e30f;
                }
                d[nt][0] = v0; d[nt][1] = v1; d[nt][2] = v2; d[nt][3] = v3;
            }

            // ---- online softmax (rows r0, r0+8), base-2 ------------------
            float mx0 = -1e30f, mx1 = -1e30f;
#pragma unroll
            for (int nt = 0; nt < 8; nt++) {
                mx0 = fmaxf(mx0, fmaxf(d[nt][0], d[nt][1]));
                mx1 = fmaxf(mx1, fmaxf(d[nt][2], d[nt][3]));
            }
            mx0 = fmaxf(mx0, __shfl_xor_sync(0xffffffffu, mx0, 1));
            mx0 = fmaxf(mx0, __shfl_xor_sync(0xffffffffu, mx0, 2));
            mx1 = fmaxf(mx1, __shfl_xor_sync(0xffffffffu, mx1, 1));
            mx1 = fmaxf(mx1, __shfl_xor_sync(0xffffffffu, mx1, 2));

            const float mn0 = fmaxf(m0r, mx0);
            const float mn1 = fmaxf(m1r, mx1);
            const float a0 = ex2f(m0r - mn0);
            const float a1 = ex2f(m1r - mn1);
            m0r = mn0; m1r = mn1;

            float rs0 = 0.0f, rs1 = 0.0f;
#pragma unroll
            for (int nt = 0; nt < 8; nt++) {
                d[nt][0] = ex2f(d[nt][0] - mn0);
                d[nt][1] = ex2f(d[nt][1] - mn0);
                d[nt][2] = ex2f(d[nt][2] - mn1);
                d[nt][3] = ex2f(d[nt][3] - mn1);
                rs0 += d[nt][0] + d[nt][1];
                rs1 += d[nt][2] + d[nt][3];
            }
            rs0 += __shfl_xor_sync(0xffffffffu, rs0, 1);
            rs0 += __shfl_xor_sync(0xffffffffu, rs0, 2);
            rs1 += __shfl_xor_sync(0xffffffffu, rs1, 1);
            rs1 += __shfl_xor_sync(0xffffffffu, rs1, 2);
            l0r = l0r * a0 + rs0;
            l1r = l1r * a1 + rs1;

#pragma unroll
            for (int nt = 0; nt < 8; nt++) {
                o[nt][0] *= a0; o[nt][1] *= a0;
                o[nt][2] *= a1; o[nt][3] *= a1;
            }

            // ---- O += P V  (main f32; corrections f16, folded per tile) ---
            uint32_t oc[8][2];
#pragma unroll
            for (int nt = 0; nt < 8; nt++) { oc[nt][0] = 0u; oc[nt][1] = 0u; }

#pragma unroll
            for (int kst = 0; kst < 4; kst++) {
                if (k0 + kst * 16 <= rmax) {       // exact: P == 0 beyond rmax
                    uint32_t pah[4], pal[4];
                    split2(d[2 * kst][0],     d[2 * kst][1],     pah[0], pal[0]);
                    split2(d[2 * kst][2],     d[2 * kst][3],     pah[1], pal[1]);
                    split2(d[2 * kst + 1][0], d[2 * kst + 1][1], pah[2], pal[2]);
                    split2(d[2 * kst + 1][2], d[2 * kst + 1][3], pah[3], pal[3]);
                    const int vrow = kst * 16 + l7 + (sub & 1) * 8;
                    const int vkof = (sub >> 1) * 8;
#pragma unroll
                    for (int g2 = 0; g2 < 4; g2++) {
                        uint32_t vh[4], vl[4];
                        const uint32_t off = (uint32_t)(vrow * ASA + g2 * 16 + vkof) * 2;
                        ldsm_x4t(vh[0], vh[1], vh[2], vh[3], cb + (uint32_t)(128 * ASA) * 2 + off);
                        ldsm_x4t(vl[0], vl[1], vl[2], vl[3], cb + (uint32_t)(192 * ASA) * 2 + off);
                        mma_f32(o[2 * g2],      pah, &vh[0]);
                        mma_f16(oc[2 * g2],     pah, &vl[0]);
                        mma_f16(oc[2 * g2],     pal, &vh[0]);
                        mma_f32(o[2 * g2 + 1],  pah, &vh[2]);
                        mma_f16(oc[2 * g2 + 1], pah, &vl[2]);
                        mma_f16(oc[2 * g2 + 1], pal, &vh[2]);
                    }
                }
            }
#pragma unroll
            for (int nt = 0; nt < 8; nt++) {
                const float2 c01 = h2f(oc[nt][0]);
                const float2 c23 = h2f(oc[nt][1]);
                o[nt][0] += c01.x; o[nt][1] += c01.y;
                o[nt][2] += c23.x; o[nt][3] += c23.y;
            }
        }
        __syncthreads();
    }

    // ---- epilogue: normalize, split to fp16 hi/lo in [b,s,h*dk] -----------
    const float i0 = 1.0f / l0r;
    const float i1 = 1.0f / l1r;
#pragma unroll
    for (int nt = 0; nt < 8; nt++) {
        const int dkc = h * 64 + nt * 8 + cpair;
        const size_t idx = ((size_t)b * SEQ + r0) * DMODEL + dkc;
        uint32_t hi, lo;
        split2(o[nt][0] * i0, o[nt][1] * i0, hi, lo);
        *(uint32_t*)(g_Oh + idx) = hi;
        *(uint32_t*)(g_Ol + idx) = lo;
        split2(o[nt][2] * i1, o[nt][3] * i1, hi, lo);
        *(uint32_t*)(g_Oh + idx + 8 * DMODEL) = hi;
        *(uint32_t*)(g_Ol + idx + 8 * DMODEL) = lo;
    }
}

// ===========================================================================
// Mega-kernel: bid [0,768) qkv | [768,1280) attn | [1280,1536) out.
// Producers precede consumers in bid order (no deadlock).
// ===========================================================================
#define MEGA_SMEM (2 * STG * 2)   // 73,728 B (attn is the max user)

__global__ __launch_bounds__(256) void mega_kernel(
    const float* __restrict__ bias, float* __restrict__ out)
{
    extern __shared__ char sbuf[];
    const int bid = blockIdx.x;
    const int tid = threadIdx.x;

    if (bid < 768) {
        const int nx  = bid / 96;
        const int rem = bid - nx * 96;
        const int my  = rem / 3;
        const int z   = rem - my * 3;
        qkv_work(sbuf, z, my * 128, nx * 128);
        __threadfence();
        __syncthreads();
        if (tid == 0) atomicAdd(&g_cntPair[nx], 1);
    } else if (bid < 1280) {
        const int abid = bid - 768;
        const int pair = abid >> 6;
        const int w64  = abid & 63;
        const int qt   = 15 - (w64 >> 2);
        const int bs   = w64 & 3;
        const int b    = bs >> 1;
        const int h    = pair * 2 + (bs & 1);
        if (tid == 0) { while (ld_acq(&g_cntPair[pair]) < 96) { } }
        __syncthreads();
        attn_work(sbuf, b, h, qt);
        __threadfence();
        __syncthreads();
        if (tid == 0) atomicAdd(&g_cntO[b * 16 + qt], 1);
    } else {
        const int obid = bid - 1280;
        const int mb   = obid >> 3;
        const int nbx  = obid & 7;
        if (tid == 0) { while (ld_acq(&g_cntO[mb]) < 16) { } }
        __syncthreads();
        out_work(sbuf, mb * 128, nbx * 128, bias, out);
    }
}

// ===========================================================================
extern "C" void kernel_launch(void* const* d_in, const int* in_sizes, int n_in,
                              void* d_out, int out_size)
{
    (void)in_sizes; (void)n_in; (void)out_size;
    const float* x  = (const float*)d_in[0];
    const float* Wq = (const float*)d_in[1];
    const float* Wk = (const float*)d_in[2];
    const float* Wv = (const float*)d_in[3];
    const float* Wo = (const float*)d_in[4];
    const float* bo = (const float*)d_in[5];
    float* out = (float*)d_out;

    cudaFuncSetAttribute(mega_kernel,
                         cudaFuncAttributeMaxDynamicSharedMemorySize, MEGA_SMEM);

    const int nTot = NX4 + 4 * NW4;                 // 2,097,152 items
    cvt_all_kernel<<<nTot / 256, 256>>>(x, Wq, Wk, Wv, Wo);
    mega_kernel<<<1536, 256, MEGA_SMEM>>>(bo, out);
}

// round 15
// speedup vs baseline: 2.0997x; 1.2951x over previous
#include <cuda_runtime.h>
#include <cuda_fp16.h>
#include <math.h>
#include <stdint.h>

#define BATCH   2
#define SEQ     2048
#define DMODEL  1024
#define NHEADS  16
#define DK      64
#define MROWS   (BATCH * SEQ)   // 4096

// -------------------- scratch (__device__ globals; no allocations) ---------
__device__ __half g_Xh[(size_t)MROWS * DMODEL];            // X rounded to fp16
__device__ __half g_Wh[4][(size_t)DMODEL * DMODEL];        // q,k,v,o hi
__device__ __half g_Wl[4][(size_t)DMODEL * DMODEL];        // q,k,v,o lo
__device__ __half g_qh[(size_t)BATCH * NHEADS * SEQ * DK]; // attention stays 3-pass
__device__ __half g_ql[(size_t)BATCH * NHEADS * SEQ * DK];
__device__ __half g_kh[(size_t)BATCH * NHEADS * SEQ * DK];
__device__ __half g_kl[(size_t)BATCH * NHEADS * SEQ * DK];
__device__ __half g_vh[(size_t)BATCH * NHEADS * SEQ * DK];
__device__ __half g_vl[(size_t)BATCH * NHEADS * SEQ * DK];
__device__ __half g_Oh[(size_t)MROWS * DMODEL];            // O rounded to fp16

// readiness counters (zeroed by cvt_all_kernel every call)
__device__ int g_cntPair[8];   // qkv CTAs done per head-pair (target 96)
__device__ int g_cntO[32];     // attn CTAs done per (b,qt) m-block (target 16)

// ===========================================================================
// warp-MMA helpers
// ===========================================================================
__device__ __forceinline__ uint32_t smem_u32(const void* p) {
    uint32_t a;
    asm("{ .reg .u64 t; cvta.to.shared.u64 t, %1; cvt.u32.u64 %0, t; }"
        : "=r"(a) : "l"(p));
    return a;
}

__device__ __forceinline__ void ldsm_x4(uint32_t& r0, uint32_t& r1,
                                        uint32_t& r2, uint32_t& r3, uint32_t addr) {
    asm volatile("ldmatrix.sync.aligned.m8n8.x4.shared.b16 {%0,%1,%2,%3}, [%4];"
                 : "=r"(r0), "=r"(r1), "=r"(r2), "=r"(r3) : "r"(addr));
}

__device__ __forceinline__ void ldsm_x4t(uint32_t& r0, uint32_t& r1,
                                         uint32_t& r2, uint32_t& r3, uint32_t addr) {
    asm volatile("ldmatrix.sync.aligned.m8n8.x4.trans.shared.b16 {%0,%1,%2,%3}, [%4];"
                 : "=r"(r0), "=r"(r1), "=r"(r2), "=r"(r3) : "r"(addr));
}

__device__ __forceinline__ void mma_f32(float* d, const uint32_t* a, const uint32_t* b) {
    asm volatile(
        "mma.sync.aligned.m16n8k16.row.col.f32.f16.f16.f32 "
        "{%0,%1,%2,%3}, {%4,%5,%6,%7}, {%8,%9}, {%0,%1,%2,%3};"
        : "+f"(d[0]), "+f"(d[1]), "+f"(d[2]), "+f"(d[3])
        : "r"(a[0]), "r"(a[1]), "r"(a[2]), "r"(a[3]), "r"(b[0]), "r"(b[1]));
}

__device__ __forceinline__ float ex2f(float x) {
    float r;
    asm("ex2.approx.f32 %0, %1;" : "=f"(r) : "f"(x));
    return r;
}

// pack two fp32 -> one f16x2 register (round-to-nearest)
__device__ __forceinline__ uint32_t pack_h2(float x, float y) {
    uint32_t h;
    asm("cvt.rn.f16x2.f32 %0, %1, %2;" : "=r"(h) : "f"(y), "f"(x));
    return h;
}

// split pair of fp32 -> packed f16x2 hi + packed f16x2 lo residual
__device__ __forceinline__ void split2(float x, float y, uint32_t& hi, uint32_t& lo) {
    uint32_t h = pack_h2(x, y);
    __half2 hh = *(__half2*)&h;
    const float rx = x - __half2float(__low2half(hh));
    const float ry = y - __half2float(__high2half(hh));
    lo = pack_h2(rx, ry);
    hi = h;
}

__device__ __forceinline__ int ld_acq(const int* p) {
    int v;
    asm volatile("ld.acquire.gpu.b32 %0, [%1];" : "=r"(v) : "l"(p) : "memory");
    return v;
}

// ===========================================================================
// cvt: X -> fp16 (hi only); W -> fp16 hi+lo. Zeroes sync counters.
// ===========================================================================
#define NX4 (MROWS * DMODEL / 4)     // 1,048,576
#define NW4 (DMODEL * DMODEL / 4)    //   262,144

__global__ void cvt_all_kernel(const float* __restrict__ x,
                               const float* __restrict__ wq,
                               const float* __restrict__ wk,
                               const float* __restrict__ wv,
                               const float* __restrict__ wo)
{
    if (blockIdx.x == 0 && threadIdx.x < 40) {
        if (threadIdx.x < 8) g_cntPair[threadIdx.x] = 0;
        else                 g_cntO[threadIdx.x - 8] = 0;
    }
    const int i = blockIdx.x * blockDim.x + threadIdx.x;
    if (i < NX4) {
        float4 v = ((const float4*)x)[i];
        ((uint2*)g_Xh)[i] = make_uint2(pack_h2(v.x, v.y), pack_h2(v.z, v.w));
        return;
    }
    const int j = i - NX4;
    const int wsel = j / NW4;
    const int idx = j - wsel * NW4;
    const float* src = (wsel == 0) ? wq : (wsel == 1) ? wk : (wsel == 2) ? wv : wo;
    float4 v = ((const float4*)src)[idx];
    uint32_t h0, h1, l0, l1;
    split2(v.x, v.y, h0, l0);
    split2(v.z, v.w, h1, l1);
    ((uint2*)g_Wh[wsel])[idx] = make_uint2(h0, h1);
    ((uint2*)g_Wl[wsel])[idx] = make_uint2(l0, l1);
}

// ===========================================================================
// 2-pass fp16 GEMM core: C = A·Bh^T + A·Bl^T, fp32 accum.
// 256 threads, warp grid 4(m) x 2(n), tile 128x128, k-chunks of 32.
// ===========================================================================
#define SA 40

__device__ __forceinline__ void gemm_tile_2p(
    const __half* __restrict__ A,
    const __half* __restrict__ Bh, const __half* __restrict__ Bl,
    int m0, int n0, float d[2][8][4], char* sbuf)
{
    __half* sA  = (__half*)sbuf;
    __half* sBh = sA  + 128 * SA;
    __half* sBl = sBh + 128 * SA;

    const int tid  = threadIdx.x;
    const int lane = tid & 31;
    const int wid  = tid >> 5;
    const int wm   = wid >> 1;
    const int wn   = wid & 1;

    const uint32_t aA = smem_u32(sA), aBh = smem_u32(sBh), aBl = smem_u32(sBl);

    const int sub  = lane >> 3, l7 = lane & 7;
    const int arow = wm * 32 + l7 + (sub & 1) * 8;
    const int akof = (sub >> 1) * 8;
    const int brow = wn * 64 + l7 + (sub >> 1) * 8;
    const int bkof = (sub & 1) * 8;

    const int grow = tid >> 2;
    const int gq   = (tid & 3) * 8;

#pragma unroll
    for (int mt = 0; mt < 2; mt++)
#pragma unroll
        for (int nt = 0; nt < 8; nt++)
#pragma unroll
            for (int c = 0; c < 4; c++) d[mt][nt][c] = 0.0f;

    uint4 va[2][3];
#pragma unroll
    for (int p = 0; p < 2; p++) {
        const size_t ga = (size_t)(m0 + p * 64 + grow) * DMODEL + gq;
        const size_t gb = (size_t)(n0 + p * 64 + grow) * DMODEL + gq;
        va[p][0] = *(const uint4*)(A  + ga);
        va[p][1] = *(const uint4*)(Bh + gb);
        va[p][2] = *(const uint4*)(Bl + gb);
    }

    for (int it = 0; it < DMODEL / 32; it++) {
        __syncthreads();
#pragma unroll
        for (int p = 0; p < 2; p++) {
            const int so = (p * 64 + grow) * SA + gq;
            *(uint4*)(sA  + so) = va[p][0];
            *(uint4*)(sBh + so) = va[p][1];
            *(uint4*)(sBl + so) = va[p][2];
        }
        if (it + 1 < DMODEL / 32) {
            const int k0 = (it + 1) * 32;
#pragma unroll
            for (int p = 0; p < 2; p++) {
                const size_t ga = (size_t)(m0 + p * 64 + grow) * DMODEL + k0 + gq;
                const size_t gb = (size_t)(n0 + p * 64 + grow) * DMODEL + k0 + gq;
                va[p][0] = *(const uint4*)(A  + ga);
                va[p][1] = *(const uint4*)(Bh + gb);
                va[p][2] = *(const uint4*)(Bl + gb);
            }
        }
        __syncthreads();

#pragma unroll
        for (int s = 0; s < 2; s++) {
            const int ks = s * 16;
            uint32_t fA[2][4], fBh[8][2], fBl[8][2];
#pragma unroll
            for (int mt = 0; mt < 2; mt++) {
                const uint32_t off = ((arow + mt * 16) * SA + ks + akof) * 2;
                ldsm_x4(fA[mt][0], fA[mt][1], fA[mt][2], fA[mt][3], aA + off);
            }
#pragma unroll
            for (int g = 0; g < 4; g++) {
                const uint32_t off = ((brow + g * 16) * SA + ks + bkof) * 2;
                ldsm_x4(fBh[2 * g][0], fBh[2 * g][1], fBh[2 * g + 1][0], fBh[2 * g + 1][1], aBh + off);
                ldsm_x4(fBl[2 * g][0], fBl[2 * g][1], fBl[2 * g + 1][0], fBl[2 * g + 1][1], aBl + off);
            }
#pragma unroll
            for (int mt = 0; mt < 2; mt++)
#pragma unroll
                for (int nt = 0; nt < 8; nt++) {
                    mma_f32(d[mt][nt], fA[mt], fBh[nt]);
                    mma_f32(d[mt][nt], fA[mt], fBl[nt]);
                }
        }
    }
}

// ---------------- qkv role: 2-pass GEMM, epilogue -> fp16 hi/lo [b,h,s,dk] -
__device__ __forceinline__ void qkv_work(char* sbuf, int z, int m0, int n0)
{
    float d[2][8][4];
    gemm_tile_2p(g_Xh, g_Wh[z], g_Wl[z], m0, n0, d, sbuf);

    __half* dh = (z == 0) ? g_qh : (z == 1 ? g_kh : g_vh);
    __half* dl = (z == 0) ? g_ql : (z == 1 ? g_kl : g_vl);
    const int lane = threadIdx.x & 31, wid = threadIdx.x >> 5;
    const int wm = wid >> 1, wn = wid & 1;
#pragma unroll
    for (int mt = 0; mt < 2; mt++) {
        const int r0 = m0 + wm * 32 + mt * 16 + (lane >> 2);
        const int b = r0 >> 11;
        const int s = r0 & (SEQ - 1);
#pragma unroll
        for (int nt = 0; nt < 8; nt++) {
            const int e  = n0 + wn * 64 + nt * 8 + (lane & 3) * 2;
            const int h  = e >> 6, dk = e & 63;
            const size_t i0 = (((size_t)b * NHEADS + h) * SEQ + s) * DK + dk;
            uint32_t hi, lo;
            split2(d[mt][nt][0], d[mt][nt][1], hi, lo);
            *(uint32_t*)(dh + i0) = hi;
            *(uint32_t*)(dl + i0) = lo;
            split2(d[mt][nt][2], d[mt][nt][3], hi, lo);
            *(uint32_t*)(dh + i0 + 8 * DK) = hi;
            *(uint32_t*)(dl + i0 + 8 * DK) = lo;
        }
    }
}

// ---------------- out-proj role: 2-pass GEMM + bias ------------------------
__device__ __forceinline__ void out_work(char* sbuf, int m0, int n0,
                                         const float* __restrict__ bias,
                                         float* __restrict__ out)
{
    float d[2][8][4];
    gemm_tile_2p(g_Oh, g_Wh[3], g_Wl[3], m0, n0, d, sbuf);

    const int lane = threadIdx.x & 31, wid = threadIdx.x >> 5;
    const int wm = wid >> 1, wn = wid & 1;
#pragma unroll
    for (int mt = 0; mt < 2; mt++) {
        const int r0 = m0 + wm * 32 + mt * 16 + (lane >> 2);
#pragma unroll
        for (int nt = 0; nt < 8; nt++) {
            const int e = n0 + wn * 64 + nt * 8 + (lane & 3) * 2;
            const float b0 = bias[e], b1 = bias[e + 1];
            float* p0 = out + (size_t)r0 * DMODEL + e;
            *(float2*)p0                 = make_float2(d[mt][nt][0] + b0, d[mt][nt][1] + b1);
            *(float2*)(p0 + 8 * DMODEL)  = make_float2(d[mt][nt][2] + b0, d[mt][nt][3] + b1);
        }
    }
}

// ---------------- attention role: 3-pass fp16, f32 accum (R11 structure) ---
#define ASA 72
#define STG (256 * ASA)

__device__ __forceinline__ void attn_work(char* sbuf, int b, int h, int qt)
{
    __half* sm = (__half*)sbuf;   // 2 * STG elems = 73,728 B

    const int tid  = threadIdx.x;
    const int lane = tid & 31;
    const int w    = tid >> 5;
    const int bh   = b * NHEADS + h;
    const int q0   = qt * 128;

    const __half* Qh = g_qh + (size_t)bh * SEQ * DK;
    const __half* Ql = g_ql + (size_t)bh * SEQ * DK;
    const __half* Kh = g_kh + (size_t)bh * SEQ * DK;
    const __half* Kl = g_kl + (size_t)bh * SEQ * DK;
    const __half* Vh = g_vh + (size_t)bh * SEQ * DK;
    const __half* Vl = g_vl + (size_t)bh * SEQ * DK;

    const uint32_t sb = smem_u32(sm);
    const int sub = lane >> 3, l7 = lane & 7;

    // ---- prologue: Q staged in stage-1 area, fragments to registers -------
    uint32_t qfh[4][4], qfl[4][4];
    {
#pragma unroll
        for (int v = 0; v < 4; v++) {
            const int item = v * 256 + tid;
            const int row = item >> 3, sec = item & 7;
            const size_t gi = (size_t)(q0 + row) * DK + sec * 8;
            *(uint4*)(sm + STG + row * ASA + sec * 8)             = *(const uint4*)(Qh + gi);
            *(uint4*)(sm + STG + 128 * ASA + row * ASA + sec * 8) = *(const uint4*)(Ql + gi);
        }
        __syncthreads();
        const int arow = w * 16 + l7 + (sub & 1) * 8;
        const int akof = (sub >> 1) * 8;
#pragma unroll
        for (int ks = 0; ks < 4; ks++) {
            const uint32_t off = (uint32_t)(STG + arow * ASA + ks * 16 + akof) * 2;
            ldsm_x4(qfh[ks][0], qfh[ks][1], qfh[ks][2], qfh[ks][3], sb + off);
            ldsm_x4(qfl[ks][0], qfl[ks][1], qfl[ks][2], qfl[ks][3], sb + (uint32_t)(128 * ASA) * 2 + off);
        }
    }

    float o[8][4];
#pragma unroll
    for (int nt = 0; nt < 8; nt++)
#pragma unroll
        for (int c = 0; c < 4; c++) o[nt][c] = 0.0f;
    float m0r = -1e30f, m1r = -1e30f, l0r = 0.0f, l1r = 0.0f;

    const int g     = lane >> 2;
    const int r0    = q0 + w * 16 + g;
    const int cpair = (lane & 3) * 2;
    const int rmax  = q0 + w * 16 + 15;

    const int ntiles = qt * 2 + 2;
    const int grow = tid >> 3, gsec = tid & 7;

    // tile 0 direct to stage 0
#pragma unroll
    for (int v = 0; v < 2; v++) {
        const int row = v * 32 + grow, sec = gsec;
        const size_t gi = (size_t)row * DK + sec * 8;
        const int so = row * ASA + sec * 8;
        *(uint4*)(sm + so)             = *(const uint4*)(Kh + gi);
        *(uint4*)(sm + 64 * ASA + so)  = *(const uint4*)(Kl + gi);
        *(uint4*)(sm + 128 * ASA + so) = *(const uint4*)(Vh + gi);
        *(uint4*)(sm + 192 * ASA + so) = *(const uint4*)(Vl + gi);
    }
    uint4 va[2][4];
    if (ntiles > 1) {
#pragma unroll
        for (int v = 0; v < 2; v++) {
            const int row = v * 32 + grow;
            const size_t gi = (size_t)(64 + row) * DK + gsec * 8;
            va[v][0] = *(const uint4*)(Kh + gi);
            va[v][1] = *(const uint4*)(Kl + gi);
            va[v][2] = *(const uint4*)(Vh + gi);
            va[v][3] = *(const uint4*)(Vl + gi);
        }
    }
    __syncthreads();

    const float sc2 = 0.18033688011f;   // 0.125 * log2(e)

    for (int kt = 0; kt < ntiles; kt++) {
        const int k0 = kt * 64;
        const uint32_t cb = sb + (uint32_t)((kt & 1) * STG) * 2;

        if (kt + 1 < ntiles) {
            __half* nx = sm + ((kt + 1) & 1) * STG;
#pragma unroll
            for (int v = 0; v < 2; v++) {
                const int row = v * 32 + grow;
                const int so = row * ASA + gsec * 8;
                *(uint4*)(nx + so)             = va[v][0];
                *(uint4*)(nx + 64 * ASA + so)  = va[v][1];
                *(uint4*)(nx + 128 * ASA + so) = va[v][2];
                *(uint4*)(nx + 192 * ASA + so) = va[v][3];
            }
            if (kt + 2 < ntiles) {
                const int nk0 = k0 + 128;
#pragma unroll
                for (int v = 0; v < 2; v++) {
                    const int row = v * 32 + grow;
                    const size_t gi = (size_t)(nk0 + row) * DK + gsec * 8;
                    va[v][0] = *(const uint4*)(Kh + gi);
                    va[v][1] = *(const uint4*)(Kl + gi);
                    va[v][2] = *(const uint4*)(Vh + gi);
                    va[v][3] = *(const uint4*)(Vl + gi);
                }
            }
        }

        if (k0 <= rmax) {
            const int nt_lim = (rmax - k0) >> 3;   // exact skip of fully-masked n-tiles
            // ---- S = Q K^T (3-pass, f32 accum) ---------------------------
            float d[8][4];
#pragma unroll
            for (int nt = 0; nt < 8; nt++)
#pragma unroll
                for (int c = 0; c < 4; c++) d[nt][c] = 0.0f;

            const int brow = l7 + (sub >> 1) * 8;
            const int bkof = (sub & 1) * 8;
#pragma unroll
            for (int ks = 0; ks < 4; ks++) {
                uint32_t fh[8][2], fl[8][2];
#pragma unroll
                for (int g2 = 0; g2 < 4; g2++) {
                    const uint32_t off = (uint32_t)((g2 * 16 + brow) * ASA + ks * 16 + bkof) * 2;
                    ldsm_x4(fh[2 * g2][0], fh[2 * g2][1], fh[2 * g2 + 1][0], fh[2 * g2 + 1][1], cb + off);
                    ldsm_x4(fl[2 * g2][0], fl[2 * g2][1], fl[2 * g2 + 1][0], fl[2 * g2 + 1][1], cb + (uint32_t)(64 * ASA) * 2 + off);
                }
#pragma unroll
                for (int nt = 0; nt < 8; nt++) {
                    if (nt <= nt_lim) {
                        mma_f32(d[nt], qfh[ks], fh[nt]);
                        mma_f32(d[nt], qfh[ks], fl[nt]);
                        mma_f32(d[nt], qfl[ks], fh[nt]);
                    }
                }
            }

            // ---- scale (base-2) + causal mask ----------------------------
            const bool need_mask = (k0 + 63 > q0 + w * 16);
#pragma unroll
            for (int nt = 0; nt < 8; nt++) {
                const int key0 = k0 + nt * 8 + cpair;
                float v0 = d[nt][0] * sc2, v1 = d[nt][1] * sc2;
                float v2 = d[nt][2] * sc2, v3 = d[nt][3] * sc2;
                if (need_mask) {
                    if (key0     > r0)     v0 = -1e30f;
                    if (key0 + 1 > r0)     v1 = -1e30f;
                    if (key0     > r0 + 8) v2 = -1e30f;
                    if (key0 + 1 > r0 + 8) v3 = -1e30f;
                }
                d[nt][0] = v0; d[nt][1] = v1; d[nt][2] = v2; d[nt][3] = v3;
            }

            // ---- online softmax (rows r0, r0+8), base-2 ------------------
            float mx0 = -1e30f, mx1 = -1e30f;
#pragma unroll
            for (int nt = 0; nt < 8; nt++) {
                mx0 = fmaxf(mx0, fmaxf(d[nt][0], d[nt][1]));
                mx1 = fmaxf(mx1, fmaxf(d[nt][2], d[nt][3]));
            }
            mx0 = fmaxf(mx0, __shfl_xor_sync(0xffffffffu, mx0, 1));
            mx0 = fmaxf(mx0, __shfl_xor_sync(0xffffffffu, mx0, 2));
            mx1 = fmaxf(mx1, __shfl_xor_sync(0xffffffffu, mx1, 1));
            mx1 = fmaxf(mx1, __shfl_xor_sync(0xffffffffu, mx1, 2));

            const float mn0 = fmaxf(m0r, mx0);
            const float mn1 = fmaxf(m1r, mx1);
            const float a0 = ex2f(m0r - mn0);
            const float a1 = ex2f(m1r - mn1);
            m0r = mn0; m1r = mn1;

            float rs0 = 0.0f, rs1 = 0.0f;
#pragma unroll
            for (int nt = 0; nt < 8; nt++) {
                d[nt][0] = ex2f(d[nt][0] - mn0);
                d[nt][1] = ex2f(d[nt][1] - mn0);
                d[nt][2] = ex2f(d[nt][2] - mn1);
                d[nt][3] = ex2f(d[nt][3] - mn1);
                rs0 += d[nt][0] + d[nt][1];
                rs1 += d[nt][2] + d[nt][3];
            }
            rs0 += __shfl_xor_sync(0xffffffffu, rs0, 1);
            rs0 += __shfl_xor_sync(0xffffffffu, rs0, 2);
            rs1 += __shfl_xor_sync(0xffffffffu, rs1, 1);
            rs1 += __shfl_xor_sync(0xffffffffu, rs1, 2);
            l0r = l0r * a0 + rs0;
            l1r = l1r * a1 + rs1;

#pragma unroll
            for (int nt = 0; nt < 8; nt++) {
                o[nt][0] *= a0; o[nt][1] *= a0;
                o[nt][2] *= a1; o[nt][3] *= a1;
            }

            // ---- O += P V (3-pass, f32 accum) ----------------------------
#pragma unroll
            for (int kst = 0; kst < 4; kst++) {
                if (k0 + kst * 16 <= rmax) {       // exact: P == 0 beyond rmax
                    uint32_t pah[4], pal[4];
                    split2(d[2 * kst][0],     d[2 * kst][1],     pah[0], pal[0]);
                    split2(d[2 * kst][2],     d[2 * kst][3],     pah[1], pal[1]);
                    split2(d[2 * kst + 1][0], d[2 * kst + 1][1], pah[2], pal[2]);
                    split2(d[2 * kst + 1][2], d[2 * kst + 1][3], pah[3], pal[3]);
                    const int vrow = kst * 16 + l7 + (sub & 1) * 8;
                    const int vkof = (sub >> 1) * 8;
#pragma unroll
                    for (int g2 = 0; g2 < 4; g2++) {
                        uint32_t vh[4], vl[4];
                        const uint32_t off = (uint32_t)(vrow * ASA + g2 * 16 + vkof) * 2;
                        ldsm_x4t(vh[0], vh[1], vh[2], vh[3], cb + (uint32_t)(128 * ASA) * 2 + off);
                        ldsm_x4t(vl[0], vl[1], vl[2], vl[3], cb + (uint32_t)(192 * ASA) * 2 + off);
                        mma_f32(o[2 * g2],     pah, &vh[0]);
                        mma_f32(o[2 * g2],     pah, &vl[0]);
                        mma_f32(o[2 * g2],     pal, &vh[0]);
                        mma_f32(o[2 * g2 + 1], pah, &vh[2]);
                        mma_f32(o[2 * g2 + 1], pah, &vl[2]);
                        mma_f32(o[2 * g2 + 1], pal, &vh[2]);
                    }
                }
            }
        }
        __syncthreads();
    }

    // ---- epilogue: normalize, round to fp16 in [b,s,h*dk] (hi only) -------
    const float i0 = 1.0f / l0r;
    const float i1 = 1.0f / l1r;
#pragma unroll
    for (int nt = 0; nt < 8; nt++) {
        const int dkc = h * 64 + nt * 8 + cpair;
        const size_t idx = ((size_t)b * SEQ + r0) * DMODEL + dkc;
        *(uint32_t*)(g_Oh + idx)               = pack_h2(o[nt][0] * i0, o[nt][1] * i0);
        *(uint32_t*)(g_Oh + idx + 8 * DMODEL)  = pack_h2(o[nt][2] * i1, o[nt][3] * i1);
    }
}

// ===========================================================================
// Mega-kernel: bid [0,768) qkv | [768,1280) attn | [1280,1536) out.
// Producers precede consumers in bid order (no deadlock).
// ===========================================================================
#define MEGA_SMEM (2 * STG * 2)   // 73,728 B (attn is the max user)

__global__ __launch_bounds__(256) void mega_kernel(
    const float* __restrict__ bias, float* __restrict__ out)
{
    extern __shared__ char sbuf[];
    const int bid = blockIdx.x;
    const int tid = threadIdx.x;

    if (bid < 768) {
        const int nx  = bid / 96;
        const int rem = bid - nx * 96;
        const int my  = rem / 3;
        const int z   = rem - my * 3;
        qkv_work(sbuf, z, my * 128, nx * 128);
        __threadfence();
        __syncthreads();
        if (tid == 0) atomicAdd(&g_cntPair[nx], 1);
    } else if (bid < 1280) {
        const int abid = bid - 768;
        const int pair = abid >> 6;
        const int w64  = abid & 63;
        const int qt   = 15 - (w64 >> 2);
        const int bs   = w64 & 3;
        const int b    = bs >> 1;
        const int h    = pair * 2 + (bs & 1);
        if (tid == 0) { while (ld_acq(&g_cntPair[pair]) < 96) { } }
        __syncthreads();
        attn_work(sbuf, b, h, qt);
        __threadfence();
        __syncthreads();
        if (tid == 0) atomicAdd(&g_cntO[b * 16 + qt], 1);
    } else {
        const int obid = bid - 1280;
        const int mb   = obid >> 3;
        const int nbx  = obid & 7;
        if (tid == 0) { while (ld_acq(&g_cntO[mb]) < 16) { } }
        __syncthreads();
        out_work(sbuf, mb * 128, nbx * 128, bias, out);
    }
}

// ===========================================================================
extern "C" void kernel_launch(void* const* d_in, const int* in_sizes, int n_in,
                              void* d_out, int out_size)
{
    (void)in_sizes; (void)n_in; (void)out_size;
    const float* x  = (const float*)d_in[0];
    const float* Wq = (const float*)d_in[1];
    const float* Wk = (const float*)d_in[2];
    const float* Wv = (const float*)d_in[3];
    const float* Wo = (const float*)d_in[4];
    const float* bo = (const float*)d_in[5];
    float* out = (float*)d_out;

    cudaFuncSetAttribute(mega_kernel,
                         cudaFuncAttributeMaxDynamicSharedMemorySize, MEGA_SMEM);

    const int nTot = NX4 + 4 * NW4;                 // 2,097,152 items
    cvt_all_kernel<<<nTot / 256, 256>>>(x, Wq, Wk, Wv, Wo);
    mega_kernel<<<1536, 256, MEGA_SMEM>>>(bo, out);
}

// round 16
// speedup vs baseline: 2.6482x; 1.2612x over previous
#include <cuda_runtime.h>
#include <cuda_fp16.h>
#include <math.h>
#include <stdint.h>

#define BATCH   2
#define SEQ     2048
#define DMODEL  1024
#define NHEADS  16
#define DK      64
#define MROWS   (BATCH * SEQ)   // 4096

// -------------------- scratch (__device__ globals; no allocations) ---------
__device__ __half g_Xh[(size_t)MROWS * DMODEL];            // X rounded to fp16
__device__ __half g_Wh[4][(size_t)DMODEL * DMODEL];        // q,k,v,o hi
__device__ __half g_Wl[4][(size_t)DMODEL * DMODEL];        // q,k,v,o lo
__device__ __half g_qh[(size_t)BATCH * NHEADS * SEQ * DK]; // fp16 Q/K/V (1-pass attn)
__device__ __half g_kh[(size_t)BATCH * NHEADS * SEQ * DK];
__device__ __half g_vh[(size_t)BATCH * NHEADS * SEQ * DK];
__device__ __half g_Oh[(size_t)MROWS * DMODEL];            // O rounded to fp16

// readiness counters (zeroed by cvt_all_kernel every call)
__device__ int g_cntPair[8];   // qkv CTAs done per head-pair (target 96)
__device__ int g_cntO[32];     // attn CTAs done per (b,qt) m-block (target 16)

// ===========================================================================
// warp-MMA helpers
// ===========================================================================
__device__ __forceinline__ uint32_t smem_u32(const void* p) {
    uint32_t a;
    asm("{ .reg .u64 t; cvta.to.shared.u64 t, %1; cvt.u32.u64 %0, t; }"
        : "=r"(a) : "l"(p));
    return a;
}

__device__ __forceinline__ void ldsm_x4(uint32_t& r0, uint32_t& r1,
                                        uint32_t& r2, uint32_t& r3, uint32_t addr) {
    asm volatile("ldmatrix.sync.aligned.m8n8.x4.shared.b16 {%0,%1,%2,%3}, [%4];"
                 : "=r"(r0), "=r"(r1), "=r"(r2), "=r"(r3) : "r"(addr));
}

__device__ __forceinline__ void ldsm_x4t(uint32_t& r0, uint32_t& r1,
                                         uint32_t& r2, uint32_t& r3, uint32_t addr) {
    asm volatile("ldmatrix.sync.aligned.m8n8.x4.trans.shared.b16 {%0,%1,%2,%3}, [%4];"
                 : "=r"(r0), "=r"(r1), "=r"(r2), "=r"(r3) : "r"(addr));
}

__device__ __forceinline__ void mma_f32(float* d, const uint32_t* a, const uint32_t* b) {
    asm volatile(
        "mma.sync.aligned.m16n8k16.row.col.f32.f16.f16.f32 "
        "{%0,%1,%2,%3}, {%4,%5,%6,%7}, {%8,%9}, {%0,%1,%2,%3};"
        : "+f"(d[0]), "+f"(d[1]), "+f"(d[2]), "+f"(d[3])
        : "r"(a[0]), "r"(a[1]), "r"(a[2]), "r"(a[3]), "r"(b[0]), "r"(b[1]));
}

__device__ __forceinline__ float ex2f(float x) {
    float r;
    asm("ex2.approx.f32 %0, %1;" : "=f"(r) : "f"(x));
    return r;
}

// pack two fp32 -> one f16x2 register (round-to-nearest)
__device__ __forceinline__ uint32_t pack_h2(float x, float y) {
    uint32_t h;
    asm("cvt.rn.f16x2.f32 %0, %1, %2;" : "=r"(h) : "f"(y), "f"(x));
    return h;
}

// split pair of fp32 -> packed f16x2 hi + packed f16x2 lo residual
__device__ __forceinline__ void split2(float x, float y, uint32_t& hi, uint32_t& lo) {
    uint32_t h = pack_h2(x, y);
    __half2 hh = *(__half2*)&h;
    const float rx = x - __half2float(__low2half(hh));
    const float ry = y - __half2float(__high2half(hh));
    lo = pack_h2(rx, ry);
    hi = h;
}

__device__ __forceinline__ int ld_acq(const int* p) {
    int v;
    asm volatile("ld.acquire.gpu.b32 %0, [%1];" : "=r"(v) : "l"(p) : "memory");
    return v;
}

// ===========================================================================
// cvt: X -> fp16 (hi only); W -> fp16 hi+lo. Zeroes sync counters.
// ===========================================================================
#define NX4 (MROWS * DMODEL / 4)     // 1,048,576
#define NW4 (DMODEL * DMODEL / 4)    //   262,144

__global__ void cvt_all_kernel(const float* __restrict__ x,
                               const float* __restrict__ wq,
                               const float* __restrict__ wk,
                               const float* __restrict__ wv,
                               const float* __restrict__ wo)
{
    if (blockIdx.x == 0 && threadIdx.x < 40) {
        if (threadIdx.x < 8) g_cntPair[threadIdx.x] = 0;
        else                 g_cntO[threadIdx.x - 8] = 0;
    }
    const int i = blockIdx.x * blockDim.x + threadIdx.x;
    if (i < NX4) {
        float4 v = ((const float4*)x)[i];
        ((uint2*)g_Xh)[i] = make_uint2(pack_h2(v.x, v.y), pack_h2(v.z, v.w));
        return;
    }
    const int j = i - NX4;
    const int wsel = j / NW4;
    const int idx = j - wsel * NW4;
    const float* src = (wsel == 0) ? wq : (wsel == 1) ? wk : (wsel == 2) ? wv : wo;
    float4 v = ((const float4*)src)[idx];
    uint32_t h0, h1, l0, l1;
    split2(v.x, v.y, h0, l0);
    split2(v.z, v.w, h1, l1);
    ((uint2*)g_Wh[wsel])[idx] = make_uint2(h0, h1);
    ((uint2*)g_Wl[wsel])[idx] = make_uint2(l0, l1);
}

// ===========================================================================
// 2-pass fp16 GEMM core: C = A·Bh^T + A·Bl^T, fp32 accum. (unchanged R15)
// ===========================================================================
#define SA 40

__device__ __forceinline__ void gemm_tile_2p(
    const __half* __restrict__ A,
    const __half* __restrict__ Bh, const __half* __restrict__ Bl,
    int m0, int n0, float d[2][8][4], char* sbuf)
{
    __half* sA  = (__half*)sbuf;
    __half* sBh = sA  + 128 * SA;
    __half* sBl = sBh + 128 * SA;

    const int tid  = threadIdx.x;
    const int lane = tid & 31;
    const int wid  = tid >> 5;
    const int wm   = wid >> 1;
    const int wn   = wid & 1;

    const uint32_t aA = smem_u32(sA), aBh = smem_u32(sBh), aBl = smem_u32(sBl);

    const int sub  = lane >> 3, l7 = lane & 7;
    const int arow = wm * 32 + l7 + (sub & 1) * 8;
    const int akof = (sub >> 1) * 8;
    const int brow = wn * 64 + l7 + (sub >> 1) * 8;
    const int bkof = (sub & 1) * 8;

    const int grow = tid >> 2;
    const int gq   = (tid & 3) * 8;

#pragma unroll
    for (int mt = 0; mt < 2; mt++)
#pragma unroll
        for (int nt = 0; nt < 8; nt++)
#pragma unroll
            for (int c = 0; c < 4; c++) d[mt][nt][c] = 0.0f;

    uint4 va[2][3];
#pragma unroll
    for (int p = 0; p < 2; p++) {
        const size_t ga = (size_t)(m0 + p * 64 + grow) * DMODEL + gq;
        const size_t gb = (size_t)(n0 + p * 64 + grow) * DMODEL + gq;
        va[p][0] = *(const uint4*)(A  + ga);
        va[p][1] = *(const uint4*)(Bh + gb);
        va[p][2] = *(const uint4*)(Bl + gb);
    }

    for (int it = 0; it < DMODEL / 32; it++) {
        __syncthreads();
#pragma unroll
        for (int p = 0; p < 2; p++) {
            const int so = (p * 64 + grow) * SA + gq;
            *(uint4*)(sA  + so) = va[p][0];
            *(uint4*)(sBh + so) = va[p][1];
            *(uint4*)(sBl + so) = va[p][2];
        }
        if (it + 1 < DMODEL / 32) {
            const int k0 = (it + 1) * 32;
#pragma unroll
            for (int p = 0; p < 2; p++) {
                const size_t ga = (size_t)(m0 + p * 64 + grow) * DMODEL + k0 + gq;
                const size_t gb = (size_t)(n0 + p * 64 + grow) * DMODEL + k0 + gq;
                va[p][0] = *(const uint4*)(A  + ga);
                va[p][1] = *(const uint4*)(Bh + gb);
                va[p][2] = *(const uint4*)(Bl + gb);
            }
        }
        __syncthreads();

#pragma unroll
        for (int s = 0; s < 2; s++) {
            const int ks = s * 16;
            uint32_t fA[2][4], fBh[8][2], fBl[8][2];
#pragma unroll
            for (int mt = 0; mt < 2; mt++) {
                const uint32_t off = ((arow + mt * 16) * SA + ks + akof) * 2;
                ldsm_x4(fA[mt][0], fA[mt][1], fA[mt][2], fA[mt][3], aA + off);
            }
#pragma unroll
            for (int g = 0; g < 4; g++) {
                const uint32_t off = ((brow + g * 16) * SA + ks + bkof) * 2;
                ldsm_x4(fBh[2 * g][0], fBh[2 * g][1], fBh[2 * g + 1][0], fBh[2 * g + 1][1], aBh + off);
                ldsm_x4(fBl[2 * g][0], fBl[2 * g][1], fBl[2 * g + 1][0], fBl[2 * g + 1][1], aBl + off);
            }
#pragma unroll
            for (int mt = 0; mt < 2; mt++)
#pragma unroll
                for (int nt = 0; nt < 8; nt++) {
                    mma_f32(d[mt][nt], fA[mt], fBh[nt]);
                    mma_f32(d[mt][nt], fA[mt], fBl[nt]);
                }
        }
    }
}

// ---------------- qkv role: 2-pass GEMM, epilogue -> plain fp16 [b,h,s,dk] -
__device__ __forceinline__ void qkv_work(char* sbuf, int z, int m0, int n0)
{
    float d[2][8][4];
    gemm_tile_2p(g_Xh, g_Wh[z], g_Wl[z], m0, n0, d, sbuf);

    __half* dh = (z == 0) ? g_qh : (z == 1 ? g_kh : g_vh);
    const int lane = threadIdx.x & 31, wid = threadIdx.x >> 5;
    const int wm = wid >> 1, wn = wid & 1;
#pragma unroll
    for (int mt = 0; mt < 2; mt++) {
        const int r0 = m0 + wm * 32 + mt * 16 + (lane >> 2);
        const int b = r0 >> 11;
        const int s = r0 & (SEQ - 1);
#pragma unroll
        for (int nt = 0; nt < 8; nt++) {
            const int e  = n0 + wn * 64 + nt * 8 + (lane & 3) * 2;
            const int h  = e >> 6, dk = e & 63;
            const size_t i0 = (((size_t)b * NHEADS + h) * SEQ + s) * DK + dk;
            *(uint32_t*)(dh + i0)          = pack_h2(d[mt][nt][0], d[mt][nt][1]);
            *(uint32_t*)(dh + i0 + 8 * DK) = pack_h2(d[mt][nt][2], d[mt][nt][3]);
        }
    }
}

// ---------------- out-proj role: 2-pass GEMM + bias ------------------------
__device__ __forceinline__ void out_work(char* sbuf, int m0, int n0,
                                         const float* __restrict__ bias,
                                         float* __restrict__ out)
{
    float d[2][8][4];
    gemm_tile_2p(g_Oh, g_Wh[3], g_Wl[3], m0, n0, d, sbuf);

    const int lane = threadIdx.x & 31, wid = threadIdx.x >> 5;
    const int wm = wid >> 1, wn = wid & 1;
#pragma unroll
    for (int mt = 0; mt < 2; mt++) {
        const int r0 = m0 + wm * 32 + mt * 16 + (lane >> 2);
#pragma unroll
        for (int nt = 0; nt < 8; nt++) {
            const int e = n0 + wn * 64 + nt * 8 + (lane & 3) * 2;
            const float b0 = bias[e], b1 = bias[e + 1];
            float* p0 = out + (size_t)r0 * DMODEL + e;
            *(float2*)p0                 = make_float2(d[mt][nt][0] + b0, d[mt][nt][1] + b1);
            *(float2*)(p0 + 8 * DMODEL)  = make_float2(d[mt][nt][2] + b0, d[mt][nt][3] + b1);
        }
    }
}

// ---------------- attention role: 1-pass fp16, f32 accum -------------------
// smem stage: Kh rows 0..63 @0, Vh rows 0..63 @64*ASA. 2 stages + Q prologue.
#define ASA 72
#define STG (128 * ASA)

__device__ __forceinline__ void attn_work(char* sbuf, int b, int h, int qt)
{
    __half* sm = (__half*)sbuf;   // 2 * STG elems = 36,864 B

    const int tid  = threadIdx.x;
    const int lane = tid & 31;
    const int w    = tid >> 5;
    const int bh   = b * NHEADS + h;
    const int q0   = qt * 128;

    const __half* Qh = g_qh + (size_t)bh * SEQ * DK;
    const __half* Kh = g_kh + (size_t)bh * SEQ * DK;
    const __half* Vh = g_vh + (size_t)bh * SEQ * DK;

    const uint32_t sb = smem_u32(sm);
    const int sub = lane >> 3, l7 = lane & 7;

    // ---- prologue: Q staged in stage-1 area (128 rows), frags to regs -----
    uint32_t qfh[4][4];
    {
#pragma unroll
        for (int v = 0; v < 4; v++) {
            const int item = v * 256 + tid;
            const int row = item >> 3, sec = item & 7;
            *(uint4*)(sm + STG + row * ASA + sec * 8) =
                *(const uint4*)(Qh + (size_t)(q0 + row) * DK + sec * 8);
        }
        __syncthreads();
        const int arow = w * 16 + l7 + (sub & 1) * 8;
        const int akof = (sub >> 1) * 8;
#pragma unroll
        for (int ks = 0; ks < 4; ks++) {
            const uint32_t off = (uint32_t)(STG + arow * ASA + ks * 16 + akof) * 2;
            ldsm_x4(qfh[ks][0], qfh[ks][1], qfh[ks][2], qfh[ks][3], sb + off);
        }
    }

    float o[8][4];
#pragma unroll
    for (int nt = 0; nt < 8; nt++)
#pragma unroll
        for (int c = 0; c < 4; c++) o[nt][c] = 0.0f;
    float m0r = -1e30f, m1r = -1e30f, l0r = 0.0f, l1r = 0.0f;

    const int g     = lane >> 2;
    const int r0    = q0 + w * 16 + g;
    const int cpair = (lane & 3) * 2;
    const int rmax  = q0 + w * 16 + 15;

    const int ntiles = qt * 2 + 2;
    const int grow = tid >> 3, gsec = tid & 7;

    // tile 0 direct to stage 0
#pragma unroll
    for (int v = 0; v < 2; v++) {
        const int row = v * 32 + grow;
        const size_t gi = (size_t)row * DK + gsec * 8;
        const int so = row * ASA + gsec * 8;
        *(uint4*)(sm + so)            = *(const uint4*)(Kh + gi);
        *(uint4*)(sm + 64 * ASA + so) = *(const uint4*)(Vh + gi);
    }
    // prefetch tile 1
    uint4 va[2][2];
    if (ntiles > 1) {
#pragma unroll
        for (int v = 0; v < 2; v++) {
            const int row = v * 32 + grow;
            const size_t gi = (size_t)(64 + row) * DK + gsec * 8;
            va[v][0] = *(const uint4*)(Kh + gi);
            va[v][1] = *(const uint4*)(Vh + gi);
        }
    }
    __syncthreads();

    const float sc2 = 0.18033688011f;   // 0.125 * log2(e)

    for (int kt = 0; kt < ntiles; kt++) {
        const int k0 = kt * 64;
        const uint32_t cb = sb + (uint32_t)((kt & 1) * STG) * 2;

        if (kt + 1 < ntiles) {
            __half* nx = sm + ((kt + 1) & 1) * STG;
#pragma unroll
            for (int v = 0; v < 2; v++) {
                const int row = v * 32 + grow;
                const int so = row * ASA + gsec * 8;
                *(uint4*)(nx + so)            = va[v][0];
                *(uint4*)(nx + 64 * ASA + so) = va[v][1];
            }
            if (kt + 2 < ntiles) {
                const int nk0 = k0 + 128;
#pragma unroll
                for (int v = 0; v < 2; v++) {
                    const int row = v * 32 + grow;
                    const size_t gi = (size_t)(nk0 + row) * DK + gsec * 8;
                    va[v][0] = *(const uint4*)(Kh + gi);
                    va[v][1] = *(const uint4*)(Vh + gi);
                }
            }
        }

        if (k0 <= rmax) {
            const int nt_lim = (rmax - k0) >> 3;   // exact skip of fully-masked n-tiles
            // ---- S = Qh Kh^T (1-pass) ------------------------------------
            float d[8][4];
#pragma unroll
            for (int nt = 0; nt < 8; nt++)
#pragma unroll
                for (int c = 0; c < 4; c++) d[nt][c] = 0.0f;

            const int brow = l7 + (sub >> 1) * 8;
            const int bkof = (sub & 1) * 8;
#pragma unroll
            for (int ks = 0; ks < 4; ks++) {
                uint32_t fh[8][2];
#pragma unroll
                for (int g2 = 0; g2 < 4; g2++) {
                    const uint32_t off = (uint32_t)((g2 * 16 + brow) * ASA + ks * 16 + bkof) * 2;
                    ldsm_x4(fh[2 * g2][0], fh[2 * g2][1], fh[2 * g2 + 1][0], fh[2 * g2 + 1][1], cb + off);
                }
#pragma unroll
                for (int nt = 0; nt < 8; nt++)
                    if (nt <= nt_lim) mma_f32(d[nt], qfh[ks], fh[nt]);
            }

            // ---- scale (base-2) + causal mask ----------------------------
            const bool need_mask = (k0 + 63 > q0 + w * 16);
#pragma unroll
            for (int nt = 0; nt < 8; nt++) {
                const int key0 = k0 + nt * 8 + cpair;
                float v0 = d[nt][0] * sc2, v1 = d[nt][1] * sc2;
                float v2 = d[nt][2] * sc2, v3 = d[nt][3] * sc2;
                if (need_mask) {
                    if (key0     > r0)     v0 = -1e30f;
                    if (key0 + 1 > r0)     v1 = -1e30f;
                    if (key0     > r0 + 8) v2 = -1e30f;
                    if (key0 + 1 > r0 + 8) v3 = -1e30f;
                }
                d[nt][0] = v0; d[nt][1] = v1; d[nt][2] = v2; d[nt][3] = v3;
            }

            // ---- online softmax (rows r0, r0+8), base-2 ------------------
            float mx0 = -1e30f, mx1 = -1e30f;
#pragma unroll
            for (int nt = 0; nt < 8; nt++) {
                mx0 = fmaxf(mx0, fmaxf(d[nt][0], d[nt][1]));
                mx1 = fmaxf(mx1, fmaxf(d[nt][2], d[nt][3]));
            }
            mx0 = fmaxf(mx0, __shfl_xor_sync(0xffffffffu, mx0, 1));
            mx0 = fmaxf(mx0, __shfl_xor_sync(0xffffffffu, mx0, 2));
            mx1 = fmaxf(mx1, __shfl_xor_sync(0xffffffffu, mx1, 1));
            mx1 = fmaxf(mx1, __shfl_xor_sync(0xffffffffu, mx1, 2));

            const float mn0 = fmaxf(m0r, mx0);
            const float mn1 = fmaxf(m1r, mx1);
            const float a0 = ex2f(m0r - mn0);
            const float a1 = ex2f(m1r - mn1);
            m0r = mn0; m1r = mn1;

            float rs0 = 0.0f, rs1 = 0.0f;
#pragma unroll
            for (int nt = 0; nt < 8; nt++) {
                d[nt][0] = ex2f(d[nt][0] - mn0);
                d[nt][1] = ex2f(d[nt][1] - mn0);
                d[nt][2] = ex2f(d[nt][2] - mn1);
                d[nt][3] = ex2f(d[nt][3] - mn1);
                rs0 += d[nt][0] + d[nt][1];
                rs1 += d[nt][2] + d[nt][3];
            }
            rs0 += __shfl_xor_sync(0xffffffffu, rs0, 1);
            rs0 += __shfl_xor_sync(0xffffffffu, rs0, 2);
            rs1 += __shfl_xor_sync(0xffffffffu, rs1, 1);
            rs1 += __shfl_xor_sync(0xffffffffu, rs1, 2);
            l0r = l0r * a0 + rs0;
            l1r = l1r * a1 + rs1;

#pragma unroll
            for (int nt = 0; nt < 8; nt++) {
                o[nt][0] *= a0; o[nt][1] *= a0;
                o[nt][2] *= a1; o[nt][3] *= a1;
            }

            // ---- O += Ph V (1-pass) --------------------------------------
#pragma unroll
            for (int kst = 0; kst < 4; kst++) {
                if (k0 + kst * 16 <= rmax) {       // exact: P == 0 beyond rmax
                    uint32_t pa[4];
                    pa[0] = pack_h2(d[2 * kst][0],     d[2 * kst][1]);
                    pa[1] = pack_h2(d[2 * kst][2],     d[2 * kst][3]);
                    pa[2] = pack_h2(d[2 * kst + 1][0], d[2 * kst + 1][1]);
                    pa[3] = pack_h2(d[2 * kst + 1][2], d[2 * kst + 1][3]);
                    const int vrow = kst * 16 + l7 + (sub & 1) * 8;
                    const int vkof = (sub >> 1) * 8;
#pragma unroll
                    for (int g2 = 0; g2 < 4; g2++) {
                        uint32_t vh[4];
                        const uint32_t off = (uint32_t)(vrow * ASA + g2 * 16 + vkof) * 2;
                        ldsm_x4t(vh[0], vh[1], vh[2], vh[3], cb + (uint32_t)(64 * ASA) * 2 + off);
                        mma_f32(o[2 * g2],     pa, &vh[0]);
                        mma_f32(o[2 * g2 + 1], pa, &vh[2]);
                    }
                }
            }
        }
        __syncthreads();
    }

    // ---- epilogue: normalize, round to fp16 in [b,s,h*dk] -----------------
    const float i0 = 1.0f / l0r;
    const float i1 = 1.0f / l1r;
#pragma unroll
    for (int nt = 0; nt < 8; nt++) {
        const int dkc = h * 64 + nt * 8 + cpair;
        const size_t idx = ((size_t)b * SEQ + r0) * DMODEL + dkc;
        *(uint32_t*)(g_Oh + idx)               = pack_h2(o[nt][0] * i0, o[nt][1] * i0);
        *(uint32_t*)(g_Oh + idx + 8 * DMODEL)  = pack_h2(o[nt][2] * i1, o[nt][3] * i1);
    }
}

// ===========================================================================
// Mega-kernel: bid [0,768) qkv | [768,1280) attn | [1280,1536) out.
// Producers precede consumers in bid order (no deadlock).
// ===========================================================================
#define GEMM_SMEM (3 * 128 * SA * 2)     // 30,720 B
#define ATTN_SMEM (2 * STG * 2)          // 36,864 B
#define MEGA_SMEM ATTN_SMEM              // attn is the max user

__global__ __launch_bounds__(256) void mega_kernel(
    const float* __restrict__ bias, float* __restrict__ out)
{
    extern __shared__ char sbuf[];
    const int bid = blockIdx.x;
    const int tid = threadIdx.x;

    if (bid < 768) {
        const int nx  = bid / 96;
        const int rem = bid - nx * 96;
        const int my  = rem / 3;
        const int z   = rem - my * 3;
        qkv_work(sbuf, z, my * 128, nx * 128);
        __threadfence();
        __syncthreads();
        if (tid == 0) atomicAdd(&g_cntPair[nx], 1);
    } else if (bid < 1280) {
        const int abid = bid - 768;
        const int pair = abid >> 6;
        const int w64  = abid & 63;
        const int qt   = 15 - (w64 >> 2);
        const int bs   = w64 & 3;
        const int b    = bs >> 1;
        const int h    = pair * 2 + (bs & 1);
        if (tid == 0) { while (ld_acq(&g_cntPair[pair]) < 96) { } }
        __syncthreads();
        attn_work(sbuf, b, h, qt);
        __threadfence();
        __syncthreads();
        if (tid == 0) atomicAdd(&g_cntO[b * 16 + qt], 1);
    } else {
        const int obid = bid - 1280;
        const int mb   = obid >> 3;
        const int nbx  = obid & 7;
        if (tid == 0) { while (ld_acq(&g_cntO[mb]) < 16) { } }
        __syncthreads();
        out_work(sbuf, mb * 128, nbx * 128, bias, out);
    }
}

// ===========================================================================
extern "C" void kernel_launch(void* const* d_in, const int* in_sizes, int n_in,
                              void* d_out, int out_size)
{
    (void)in_sizes; (void)n_in; (void)out_size;
    const float* x  = (const float*)d_in[0];
    const float* Wq = (const float*)d_in[1];
    const float* Wk = (const float*)d_in[2];
    const float* Wv = (const float*)d_in[3];
    const float* Wo = (const float*)d_in[4];
    const float* bo = (const float*)d_in[5];
    float* out = (float*)d_out;

    cudaFuncSetAttribute(mega_kernel,
                         cudaFuncAttributeMaxDynamicSharedMemorySize, MEGA_SMEM);

    const int nTot = NX4 + 4 * NW4;                 // 2,097,152 items
    cvt_all_kernel<<<nTot / 256, 256>>>(x, Wq, Wk, Wv, Wo);
    mega_kernel<<<1536, 256, MEGA_SMEM>>>(bo, out);
}

// round 17
// speedup vs baseline: 3.0056x; 1.1349x over previous
#include <cuda_runtime.h>
#include <cuda_fp16.h>
#include <math.h>
#include <stdint.h>

#define BATCH   2
#define SEQ     2048
#define DMODEL  1024
#define NHEADS  16
#define DK      64
#define MROWS   (BATCH * SEQ)   // 4096

// -------------------- scratch (__device__ globals; no allocations) ---------
__device__ __half g_Xh[(size_t)MROWS * DMODEL];            // X rounded to fp16
__device__ __half g_Wh[4][(size_t)DMODEL * DMODEL];        // q,k,v,o hi
__device__ __half g_Wl[2][(size_t)DMODEL * DMODEL];        // q,k lo (v,o are 1-pass)
__device__ __half g_qh[(size_t)BATCH * NHEADS * SEQ * DK];
__device__ __half g_kh[(size_t)BATCH * NHEADS * SEQ * DK];
__device__ __half g_vh[(size_t)BATCH * NHEADS * SEQ * DK];
__device__ __half g_Oh[(size_t)MROWS * DMODEL];            // O rounded to fp16

// readiness counters (zeroed by cvt_all_kernel every call)
__device__ int g_cntPair[8];   // qkv CTAs done per head-pair (target 96)
__device__ int g_cntO[32];     // attn CTAs done per (b,qt) m-block (target 16)

// ===========================================================================
// warp-MMA helpers
// ===========================================================================
__device__ __forceinline__ uint32_t smem_u32(const void* p) {
    uint32_t a;
    asm("{ .reg .u64 t; cvta.to.shared.u64 t, %1; cvt.u32.u64 %0, t; }"
        : "=r"(a) : "l"(p));
    return a;
}

__device__ __forceinline__ void ldsm_x4(uint32_t& r0, uint32_t& r1,
                                        uint32_t& r2, uint32_t& r3, uint32_t addr) {
    asm volatile("ldmatrix.sync.aligned.m8n8.x4.shared.b16 {%0,%1,%2,%3}, [%4];"
                 : "=r"(r0), "=r"(r1), "=r"(r2), "=r"(r3) : "r"(addr));
}

__device__ __forceinline__ void ldsm_x4t(uint32_t& r0, uint32_t& r1,
                                         uint32_t& r2, uint32_t& r3, uint32_t addr) {
    asm volatile("ldmatrix.sync.aligned.m8n8.x4.trans.shared.b16 {%0,%1,%2,%3}, [%4];"
                 : "=r"(r0), "=r"(r1), "=r"(r2), "=r"(r3) : "r"(addr));
}

__device__ __forceinline__ void mma_f32(float* d, const uint32_t* a, const uint32_t* b) {
    asm volatile(
        "mma.sync.aligned.m16n8k16.row.col.f32.f16.f16.f32 "
        "{%0,%1,%2,%3}, {%4,%5,%6,%7}, {%8,%9}, {%0,%1,%2,%3};"
        : "+f"(d[0]), "+f"(d[1]), "+f"(d[2]), "+f"(d[3])
        : "r"(a[0]), "r"(a[1]), "r"(a[2]), "r"(a[3]), "r"(b[0]), "r"(b[1]));
}

__device__ __forceinline__ float ex2f(float x) {
    float r;
    asm("ex2.approx.f32 %0, %1;" : "=f"(r) : "f"(x));
    return r;
}

__device__ __forceinline__ uint32_t pack_h2(float x, float y) {
    uint32_t h;
    asm("cvt.rn.f16x2.f32 %0, %1, %2;" : "=r"(h) : "f"(y), "f"(x));
    return h;
}

__device__ __forceinline__ void split2(float x, float y, uint32_t& hi, uint32_t& lo) {
    uint32_t h = pack_h2(x, y);
    __half2 hh = *(__half2*)&h;
    const float rx = x - __half2float(__low2half(hh));
    const float ry = y - __half2float(__high2half(hh));
    lo = pack_h2(rx, ry);
    hi = h;
}

__device__ __forceinline__ int ld_acq(const int* p) {
    int v;
    asm volatile("ld.acquire.gpu.b32 %0, [%1];" : "=r"(v) : "l"(p) : "memory");
    return v;
}

// ===========================================================================
// cvt: X -> fp16; Wq/Wk -> hi+lo; Wv/Wo -> hi only. Zeroes sync counters.
// ===========================================================================
#define NX4 (MROWS * DMODEL / 4)     // 1,048,576
#define NW4 (DMODEL * DMODEL / 4)    //   262,144

__global__ void cvt_all_kernel(const float* __restrict__ x,
                               const float* __restrict__ wq,
                               const float* __restrict__ wk,
                               const float* __restrict__ wv,
                               const float* __restrict__ wo)
{
    if (blockIdx.x == 0 && threadIdx.x < 40) {
        if (threadIdx.x < 8) g_cntPair[threadIdx.x] = 0;
        else                 g_cntO[threadIdx.x - 8] = 0;
    }
    const int i = blockIdx.x * blockDim.x + threadIdx.x;
    if (i < NX4) {
        float4 v = ((const float4*)x)[i];
        ((uint2*)g_Xh)[i] = make_uint2(pack_h2(v.x, v.y), pack_h2(v.z, v.w));
        return;
    }
    const int j = i - NX4;
    const int wsel = j / NW4;
    const int idx = j - wsel * NW4;
    const float* src = (wsel == 0) ? wq : (wsel == 1) ? wk : (wsel == 2) ? wv : wo;
    float4 v = ((const float4*)src)[idx];
    if (wsel < 2) {
        uint32_t h0, h1, l0, l1;
        split2(v.x, v.y, h0, l0);
        split2(v.z, v.w, h1, l1);
        ((uint2*)g_Wh[wsel])[idx] = make_uint2(h0, h1);
        ((uint2*)g_Wl[wsel])[idx] = make_uint2(l0, l1);
    } else {
        ((uint2*)g_Wh[wsel])[idx] = make_uint2(pack_h2(v.x, v.y), pack_h2(v.z, v.w));
    }
}

// ===========================================================================
// GEMM cores: 2-pass (C = A·Bh^T + A·Bl^T) and 1-pass (C = A·Bh^T), f32 accum
// ===========================================================================
#define SA 40

__device__ __forceinline__ void gemm_tile_2p(
    const __half* __restrict__ A,
    const __half* __restrict__ Bh, const __half* __restrict__ Bl,
    int m0, int n0, float d[2][8][4], char* sbuf)
{
    __half* sA  = (__half*)sbuf;
    __half* sBh = sA  + 128 * SA;
    __half* sBl = sBh + 128 * SA;

    const int tid  = threadIdx.x;
    const int lane = tid & 31;
    const int wid  = tid >> 5;
    const int wm   = wid >> 1;
    const int wn   = wid & 1;

    const uint32_t aA = smem_u32(sA), aBh = smem_u32(sBh), aBl = smem_u32(sBl);

    const int sub  = lane >> 3, l7 = lane & 7;
    const int arow = wm * 32 + l7 + (sub & 1) * 8;
    const int akof = (sub >> 1) * 8;
    const int brow = wn * 64 + l7 + (sub >> 1) * 8;
    const int bkof = (sub & 1) * 8;

    const int grow = tid >> 2;
    const int gq   = (tid & 3) * 8;

#pragma unroll
    for (int mt = 0; mt < 2; mt++)
#pragma unroll
        for (int nt = 0; nt < 8; nt++)
#pragma unroll
            for (int c = 0; c < 4; c++) d[mt][nt][c] = 0.0f;

    uint4 va[2][3];
#pragma unroll
    for (int p = 0; p < 2; p++) {
        const size_t ga = (size_t)(m0 + p * 64 + grow) * DMODEL + gq;
        const size_t gb = (size_t)(n0 + p * 64 + grow) * DMODEL + gq;
        va[p][0] = *(const uint4*)(A  + ga);
        va[p][1] = *(const uint4*)(Bh + gb);
        va[p][2] = *(const uint4*)(Bl + gb);
    }

    for (int it = 0; it < DMODEL / 32; it++) {
        __syncthreads();
#pragma unroll
        for (int p = 0; p < 2; p++) {
            const int so = (p * 64 + grow) * SA + gq;
            *(uint4*)(sA  + so) = va[p][0];
            *(uint4*)(sBh + so) = va[p][1];
            *(uint4*)(sBl + so) = va[p][2];
        }
        if (it + 1 < DMODEL / 32) {
            const int k0 = (it + 1) * 32;
#pragma unroll
            for (int p = 0; p < 2; p++) {
                const size_t ga = (size_t)(m0 + p * 64 + grow) * DMODEL + k0 + gq;
                const size_t gb = (size_t)(n0 + p * 64 + grow) * DMODEL + k0 + gq;
                va[p][0] = *(const uint4*)(A  + ga);
                va[p][1] = *(const uint4*)(Bh + gb);
                va[p][2] = *(const uint4*)(Bl + gb);
            }
        }
        __syncthreads();

#pragma unroll
        for (int s = 0; s < 2; s++) {
            const int ks = s * 16;
            uint32_t fA[2][4], fBh[8][2], fBl[8][2];
#pragma unroll
            for (int mt = 0; mt < 2; mt++) {
                const uint32_t off = ((arow + mt * 16) * SA + ks + akof) * 2;
                ldsm_x4(fA[mt][0], fA[mt][1], fA[mt][2], fA[mt][3], aA + off);
            }
#pragma unroll
            for (int g = 0; g < 4; g++) {
                const uint32_t off = ((brow + g * 16) * SA + ks + bkof) * 2;
                ldsm_x4(fBh[2 * g][0], fBh[2 * g][1], fBh[2 * g + 1][0], fBh[2 * g + 1][1], aBh + off);
                ldsm_x4(fBl[2 * g][0], fBl[2 * g][1], fBl[2 * g + 1][0], fBl[2 * g + 1][1], aBl + off);
            }
#pragma unroll
            for (int mt = 0; mt < 2; mt++)
#pragma unroll
                for (int nt = 0; nt < 8; nt++) {
                    mma_f32(d[mt][nt], fA[mt], fBh[nt]);
                    mma_f32(d[mt][nt], fA[mt], fBl[nt]);
                }
        }
    }
}

__device__ __forceinline__ void gemm_tile_1p(
    const __half* __restrict__ A, const __half* __restrict__ Bh,
    int m0, int n0, float d[2][8][4], char* sbuf)
{
    __half* sA  = (__half*)sbuf;
    __half* sBh = sA + 128 * SA;

    const int tid  = threadIdx.x;
    const int lane = tid & 31;
    const int wid  = tid >> 5;
    const int wm   = wid >> 1;
    const int wn   = wid & 1;

    const uint32_t aA = smem_u32(sA), aBh = smem_u32(sBh);

    const int sub  = lane >> 3, l7 = lane & 7;
    const int arow = wm * 32 + l7 + (sub & 1) * 8;
    const int akof = (sub >> 1) * 8;
    const int brow = wn * 64 + l7 + (sub >> 1) * 8;
    const int bkof = (sub & 1) * 8;

    const int grow = tid >> 2;
    const int gq   = (tid & 3) * 8;

#pragma unroll
    for (int mt = 0; mt < 2; mt++)
#pragma unroll
        for (int nt = 0; nt < 8; nt++)
#pragma unroll
            for (int c = 0; c < 4; c++) d[mt][nt][c] = 0.0f;

    uint4 va[2][2];
#pragma unroll
    for (int p = 0; p < 2; p++) {
        const size_t ga = (size_t)(m0 + p * 64 + grow) * DMODEL + gq;
        const size_t gb = (size_t)(n0 + p * 64 + grow) * DMODEL + gq;
        va[p][0] = *(const uint4*)(A  + ga);
        va[p][1] = *(const uint4*)(Bh + gb);
    }

    for (int it = 0; it < DMODEL / 32; it++) {
        __syncthreads();
#pragma unroll
        for (int p = 0; p < 2; p++) {
            const int so = (p * 64 + grow) * SA + gq;
            *(uint4*)(sA  + so) = va[p][0];
            *(uint4*)(sBh + so) = va[p][1];
        }
        if (it + 1 < DMODEL / 32) {
            const int k0 = (it + 1) * 32;
#pragma unroll
            for (int p = 0; p < 2; p++) {
                const size_t ga = (size_t)(m0 + p * 64 + grow) * DMODEL + k0 + gq;
                const size_t gb = (size_t)(n0 + p * 64 + grow) * DMODEL + k0 + gq;
                va[p][0] = *(const uint4*)(A  + ga);
                va[p][1] = *(const uint4*)(Bh + gb);
            }
        }
        __syncthreads();

#pragma unroll
        for (int s = 0; s < 2; s++) {
            const int ks = s * 16;
            uint32_t fA[2][4], fBh[8][2];
#pragma unroll
            for (int mt = 0; mt < 2; mt++) {
                const uint32_t off = ((arow + mt * 16) * SA + ks + akof) * 2;
                ldsm_x4(fA[mt][0], fA[mt][1], fA[mt][2], fA[mt][3], aA + off);
            }
#pragma unroll
            for (int g = 0; g < 4; g++) {
                const uint32_t off = ((brow + g * 16) * SA + ks + bkof) * 2;
                ldsm_x4(fBh[2 * g][0], fBh[2 * g][1], fBh[2 * g + 1][0], fBh[2 * g + 1][1], aBh + off);
            }
#pragma unroll
            for (int mt = 0; mt < 2; mt++)
#pragma unroll
                for (int nt = 0; nt < 8; nt++)
                    mma_f32(d[mt][nt], fA[mt], fBh[nt]);
        }
    }
}

// ---------------- qkv role: Q/K 2-pass, V 1-pass; epilogue -> fp16 ---------
__device__ __forceinline__ void qkv_work(char* sbuf, int z, int m0, int n0)
{
    float d[2][8][4];
    if (z < 2) gemm_tile_2p(g_Xh, g_Wh[z], g_Wl[z], m0, n0, d, sbuf);
    else       gemm_tile_1p(g_Xh, g_Wh[2], m0, n0, d, sbuf);

    __half* dh = (z == 0) ? g_qh : (z == 1 ? g_kh : g_vh);
    const int lane = threadIdx.x & 31, wid = threadIdx.x >> 5;
    const int wm = wid >> 1, wn = wid & 1;
#pragma unroll
    for (int mt = 0; mt < 2; mt++) {
        const int r0 = m0 + wm * 32 + mt * 16 + (lane >> 2);
        const int b = r0 >> 11;
        const int s = r0 & (SEQ - 1);
#pragma unroll
        for (int nt = 0; nt < 8; nt++) {
            const int e  = n0 + wn * 64 + nt * 8 + (lane & 3) * 2;
            const int h  = e >> 6, dk = e & 63;
            const size_t i0 = (((size_t)b * NHEADS + h) * SEQ + s) * DK + dk;
            *(uint32_t*)(dh + i0)          = pack_h2(d[mt][nt][0], d[mt][nt][1]);
            *(uint32_t*)(dh + i0 + 8 * DK) = pack_h2(d[mt][nt][2], d[mt][nt][3]);
        }
    }
}

// ---------------- out-proj role: 1-pass GEMM + bias ------------------------
__device__ __forceinline__ void out_work(char* sbuf, int m0, int n0,
                                         const float* __restrict__ bias,
                                         float* __restrict__ out)
{
    float d[2][8][4];
    gemm_tile_1p(g_Oh, g_Wh[3], m0, n0, d, sbuf);

    const int lane = threadIdx.x & 31, wid = threadIdx.x >> 5;
    const int wm = wid >> 1, wn = wid & 1;
#pragma unroll
    for (int mt = 0; mt < 2; mt++) {
        const int r0 = m0 + wm * 32 + mt * 16 + (lane >> 2);
#pragma unroll
        for (int nt = 0; nt < 8; nt++) {
            const int e = n0 + wn * 64 + nt * 8 + (lane & 3) * 2;
            const float b0 = bias[e], b1 = bias[e + 1];
            float* p0 = out + (size_t)r0 * DMODEL + e;
            *(float2*)p0                 = make_float2(d[mt][nt][0] + b0, d[mt][nt][1] + b1);
            *(float2*)(p0 + 8 * DMODEL)  = make_float2(d[mt][nt][2] + b0, d[mt][nt][3] + b1);
        }
    }
}

// ---------------- attention role: 1-pass fp16, f32 accum (unchanged R16) ---
#define ASA 72
#define STG (128 * ASA)

__device__ __forceinline__ void attn_work(char* sbuf, int b, int h, int qt)
{
    __half* sm = (__half*)sbuf;   // 2 * STG elems = 36,864 B

    const int tid  = threadIdx.x;
    const int lane = tid & 31;
    const int w    = tid >> 5;
    const int bh   = b * NHEADS + h;
    const int q0   = qt * 128;

    const __half* Qh = g_qh + (size_t)bh * SEQ * DK;
    const __half* Kh = g_kh + (size_t)bh * SEQ * DK;
    const __half* Vh = g_vh + (size_t)bh * SEQ * DK;

    const uint32_t sb = smem_u32(sm);
    const int sub = lane >> 3, l7 = lane & 7;

    uint32_t qfh[4][4];
    {
#pragma unroll
        for (int v = 0; v < 4; v++) {
            const int item = v * 256 + tid;
            const int row = item >> 3, sec = item & 7;
            *(uint4*)(sm + STG + row * ASA + sec * 8) =
                *(const uint4*)(Qh + (size_t)(q0 + row) * DK + sec * 8);
        }
        __syncthreads();
        const int arow = w * 16 + l7 + (sub & 1) * 8;
        const int akof = (sub >> 1) * 8;
#pragma unroll
        for (int ks = 0; ks < 4; ks++) {
            const uint32_t off = (uint32_t)(STG + arow * ASA + ks * 16 + akof) * 2;
            ldsm_x4(qfh[ks][0], qfh[ks][1], qfh[ks][2], qfh[ks][3], sb + off);
        }
    }

    float o[8][4];
#pragma unroll
    for (int nt = 0; nt < 8; nt++)
#pragma unroll
        for (int c = 0; c < 4; c++) o[nt][c] = 0.0f;
    float m0r = -1e30f, m1r = -1e30f, l0r = 0.0f, l1r = 0.0f;

    const int g     = lane >> 2;
    const int r0    = q0 + w * 16 + g;
    const int cpair = (lane & 3) * 2;
    const int rmax  = q0 + w * 16 + 15;

    const int ntiles = qt * 2 + 2;
    const int grow = tid >> 3, gsec = tid & 7;

#pragma unroll
    for (int v = 0; v < 2; v++) {
        const int row = v * 32 + grow;
        const size_t gi = (size_t)row * DK + gsec * 8;
        const int so = row * ASA + gsec * 8;
        *(uint4*)(sm + so)            = *(const uint4*)(Kh + gi);
        *(uint4*)(sm + 64 * ASA + so) = *(const uint4*)(Vh + gi);
    }
    uint4 va[2][2];
    if (ntiles > 1) {
#pragma unroll
        for (int v = 0; v < 2; v++) {
            const int row = v * 32 + grow;
            const size_t gi = (size_t)(64 + row) * DK + gsec * 8;
            va[v][0] = *(const uint4*)(Kh + gi);
            va[v][1] = *(const uint4*)(Vh + gi);
        }
    }
    __syncthreads();

    const float sc2 = 0.18033688011f;   // 0.125 * log2(e)

    for (int kt = 0; kt < ntiles; kt++) {
        const int k0 = kt * 64;
        const uint32_t cb = sb + (uint32_t)((kt & 1) * STG) * 2;

        if (kt + 1 < ntiles) {
            __half* nx = sm + ((kt + 1) & 1) * STG;
#pragma unroll
            for (int v = 0; v < 2; v++) {
                const int row = v * 32 + grow;
                const int so = row * ASA + gsec * 8;
                *(uint4*)(nx + so)            = va[v][0];
                *(uint4*)(nx + 64 * ASA + so) = va[v][1];
            }
            if (kt + 2 < ntiles) {
                const int nk0 = k0 + 128;
#pragma unroll
                for (int v = 0; v < 2; v++) {
                    const int row = v * 32 + grow;
                    const size_t gi = (size_t)(nk0 + row) * DK + gsec * 8;
                    va[v][0] = *(const uint4*)(Kh + gi);
                    va[v][1] = *(const uint4*)(Vh + gi);
                }
            }
        }

        if (k0 <= rmax) {
            const int nt_lim = (rmax - k0) >> 3;
            float d[8][4];
#pragma unroll
            for (int nt = 0; nt < 8; nt++)
#pragma unroll
                for (int c = 0; c < 4; c++) d[nt][c] = 0.0f;

            const int brow = l7 + (sub >> 1) * 8;
            const int bkof = (sub & 1) * 8;
#pragma unroll
            for (int ks = 0; ks < 4; ks++) {
                uint32_t fh[8][2];
#pragma unroll
                for (int g2 = 0; g2 < 4; g2++) {
                    const uint32_t off = (uint32_t)((g2 * 16 + brow) * ASA + ks * 16 + bkof) * 2;
                    ldsm_x4(fh[2 * g2][0], fh[2 * g2][1], fh[2 * g2 + 1][0], fh[2 * g2 + 1][1], cb + off);
                }
#pragma unroll
                for (int nt = 0; nt < 8; nt++)
                    if (nt <= nt_lim) mma_f32(d[nt], qfh[ks], fh[nt]);
            }

            const bool need_mask = (k0 + 63 > q0 + w * 16);
#pragma unroll
            for (int nt = 0; nt < 8; nt++) {
                const int key0 = k0 + nt * 8 + cpair;
                float v0 = d[nt][0] * sc2, v1 = d[nt][1] * sc2;
                float v2 = d[nt][2] * sc2, v3 = d[nt][3] * sc2;
                if (need_mask) {
                    if (key0     > r0)     v0 = -1e30f;
                    if (key0 + 1 > r0)     v1 = -1e30f;
                    if (key0     > r0 + 8) v2 = -1e30f;
                    if (key0 + 1 > r0 + 8) v3 = -1e30f;
                }
                d[nt][0] = v0; d[nt][1] = v1; d[nt][2] = v2; d[nt][3] = v3;
            }

            float mx0 = -1e30f, mx1 = -1e30f;
#pragma unroll
            for (int nt = 0; nt < 8; nt++) {
                mx0 = fmaxf(mx0, fmaxf(d[nt][0], d[nt][1]));
                mx1 = fmaxf(mx1, fmaxf(d[nt][2], d[nt][3]));
            }
            mx0 = fmaxf(mx0, __shfl_xor_sync(0xffffffffu, mx0, 1));
            mx0 = fmaxf(mx0, __shfl_xor_sync(0xffffffffu, mx0, 2));
            mx1 = fmaxf(mx1, __shfl_xor_sync(0xffffffffu, mx1, 1));
            mx1 = fmaxf(mx1, __shfl_xor_sync(0xffffffffu, mx1, 2));

            const float mn0 = fmaxf(m0r, mx0);
            const float mn1 = fmaxf(m1r, mx1);
            const float a0 = ex2f(m0r - mn0);
            const float a1 = ex2f(m1r - mn1);
            m0r = mn0; m1r = mn1;

            float rs0 = 0.0f, rs1 = 0.0f;
#pragma unroll
            for (int nt = 0; nt < 8; nt++) {
                d[nt][0] = ex2f(d[nt][0] - mn0);
                d[nt][1] = ex2f(d[nt][1] - mn0);
                d[nt][2] = ex2f(d[nt][2] - mn1);
                d[nt][3] = ex2f(d[nt][3] - mn1);
                rs0 += d[nt][0] + d[nt][1];
                rs1 += d[nt][2] + d[nt][3];
            }
            rs0 += __shfl_xor_sync(0xffffffffu, rs0, 1);
            rs0 += __shfl_xor_sync(0xffffffffu, rs0, 2);
            rs1 += __shfl_xor_sync(0xffffffffu, rs1, 1);
            rs1 += __shfl_xor_sync(0xffffffffu, rs1, 2);
            l0r = l0r * a0 + rs0;
            l1r = l1r * a1 + rs1;

#pragma unroll
            for (int nt = 0; nt < 8; nt++) {
                o[nt][0] *= a0; o[nt][1] *= a0;
                o[nt][2] *= a1; o[nt][3] *= a1;
            }

#pragma unroll
            for (int kst = 0; kst < 4; kst++) {
                if (k0 + kst * 16 <= rmax) {
                    uint32_t pa[4];
                    pa[0] = pack_h2(d[2 * kst][0],     d[2 * kst][1]);
                    pa[1] = pack_h2(d[2 * kst][2],     d[2 * kst][3]);
                    pa[2] = pack_h2(d[2 * kst + 1][0], d[2 * kst + 1][1]);
                    pa[3] = pack_h2(d[2 * kst + 1][2], d[2 * kst + 1][3]);
                    const int vrow = kst * 16 + l7 + (sub & 1) * 8;
                    const int vkof = (sub >> 1) * 8;
#pragma unroll
                    for (int g2 = 0; g2 < 4; g2++) {
                        uint32_t vh[4];
                        const uint32_t off = (uint32_t)(vrow * ASA + g2 * 16 + vkof) * 2;
                        ldsm_x4t(vh[0], vh[1], vh[2], vh[3], cb + (uint32_t)(64 * ASA) * 2 + off);
                        mma_f32(o[2 * g2],     pa, &vh[0]);
                        mma_f32(o[2 * g2 + 1], pa, &vh[2]);
                    }
                }
            }
        }
        __syncthreads();
    }

    const float i0 = 1.0f / l0r;
    const float i1 = 1.0f / l1r;
#pragma unroll
    for (int nt = 0; nt < 8; nt++) {
        const int dkc = h * 64 + nt * 8 + cpair;
        const size_t idx = ((size_t)b * SEQ + r0) * DMODEL + dkc;
        *(uint32_t*)(g_Oh + idx)               = pack_h2(o[nt][0] * i0, o[nt][1] * i0);
        *(uint32_t*)(g_Oh + idx + 8 * DMODEL)  = pack_h2(o[nt][2] * i1, o[nt][3] * i1);
    }
}

// ===========================================================================
// Mega-kernel: bid [0,768) qkv | [768,1280) attn | [1280,1536) out.
// Producers precede consumers in bid order (no deadlock).
// ===========================================================================
#define ATTN_SMEM (2 * STG * 2)          // 36,864 B (max user)
#define MEGA_SMEM ATTN_SMEM

__global__ __launch_bounds__(256) void mega_kernel(
    const float* __restrict__ bias, float* __restrict__ out)
{
    extern __shared__ char sbuf[];
    const int bid = blockIdx.x;
    const int tid = threadIdx.x;

    if (bid < 768) {
        const int nx  = bid / 96;
        const int rem = bid - nx * 96;
        const int my  = rem / 3;
        const int z   = rem - my * 3;
        qkv_work(sbuf, z, my * 128, nx * 128);
        __threadfence();
        __syncthreads();
        if (tid == 0) atomicAdd(&g_cntPair[nx], 1);
    } else if (bid < 1280) {
        const int abid = bid - 768;
        const int pair = abid >> 6;
        const int w64  = abid & 63;
        const int qt   = 15 - (w64 >> 2);
        const int bs   = w64 & 3;
        const int b    = bs >> 1;
        const int h    = pair * 2 + (bs & 1);
        if (tid == 0) { while (ld_acq(&g_cntPair[pair]) < 96) { } }
        __syncthreads();
        attn_work(sbuf, b, h, qt);
        __threadfence();
        __syncthreads();
        if (tid == 0) atomicAdd(&g_cntO[b * 16 + qt], 1);
    } else {
        const int obid = bid - 1280;
        const int mb   = obid >> 3;
        const int nbx  = obid & 7;
        if (tid == 0) { while (ld_acq(&g_cntO[mb]) < 16) { } }
        __syncthreads();
        out_work(sbuf, mb * 128, nbx * 128, bias, out);
    }
}

// ===========================================================================
extern "C" void kernel_launch(void* const* d_in, const int* in_sizes, int n_in,
                              void* d_out, int out_size)
{
    (void)in_sizes; (void)n_in; (void)out_size;
    const float* x  = (const float*)d_in[0];
    const float* Wq = (const float*)d_in[1];
    const float* Wk = (const float*)d_in[2];
    const float* Wv = (const float*)d_in[3];
    const float* Wo = (const float*)d_in[4];
    const float* bo = (const float*)d_in[5];
    float* out = (float*)d_out;

    cudaFuncSetAttribute(mega_kernel,
                         cudaFuncAttributeMaxDynamicSharedMemorySize, MEGA_SMEM);

    const int nTot = NX4 + 4 * NW4;                 // 2,097,152 items
    cvt_all_kernel<<<nTot / 256, 256>>>(x, Wq, Wk, Wv, Wo);
    mega_kernel<<<1536, 256, MEGA_SMEM>>>(bo, out);
}